// round 5
// baseline (speedup 1.0000x reference)
#include <cuda_runtime.h>

#define NN   50000
#define NE   640000
#define NF   128
#define HID  256
#define UF   64

// Scratch (allocation-free: __device__ globals)
__device__ float g_P[NN * HID];     // x @ W1[:128] + b1, per node
__device__ float g_agg[NN * HID];   // scatter-sum of edge messages
__device__ float g_cnt[NN];         // edge counts per destination node
__device__ int   g_is64;            // 1 if index arrays are int64, 0 if int32

// ---------------------------------------------------------------------------
// Zero scratch + detect index dtype (int32 vs int64).
// For int32 data read as int64, value = lo + hi*2^32 with hi = a neighboring
// index (generally nonzero) -> out of [0,NN) -> classified int32.
__global__ void zero_kernel(const void* ei_raw) {
    int idx = blockIdx.x * blockDim.x + threadIdx.x;
    int stride = gridDim.x * blockDim.x;
    for (int i = idx; i < NN * HID; i += stride) g_agg[i] = 0.f;
    for (int i = idx; i < NN; i += stride) g_cnt[i] = 0.f;
    if (blockIdx.x == 0 && threadIdx.x == 0) {
        const long long* p = (const long long*)ei_raw;
        int ok = 1;
        for (int i = 0; i < 1024; i++) {
            long long v = p[i];
            if (v < 0 || v >= NN) { ok = 0; break; }
        }
        g_is64 = ok;
    }
}

__device__ __forceinline__ int load_index(const void* p, long long i) {
    long long v = g_is64 ? ((const long long*)p)[i] : (long long)((const int*)p)[i];
    if (v < 0) v = 0;
    if (v >= NN) v = NN - 1;
    return (int)v;
}

// ---------------------------------------------------------------------------
// 16-deep k-step: 4 rows x 16 cols micro-tile FMA
__device__ __forceinline__ void fma_step4(float a0, float a1, float a2, float a3,
                                          const float* __restrict__ bp,
                                          float acc[4][16]) {
#pragma unroll
    for (int j4 = 0; j4 < 4; j4++) {
        float4 bv = *(const float4*)(bp + 4 * j4);
        float b[4] = {bv.x, bv.y, bv.z, bv.w};
#pragma unroll
        for (int jj = 0; jj < 4; jj++) {
            int j = j4 * 4 + jj;
            acc[0][j] = fmaf(a0, b[jj], acc[0][j]);
            acc[1][j] = fmaf(a1, b[jj], acc[1][j]);
            acc[2][j] = fmaf(a2, b[jj], acc[2][j]);
            acc[3][j] = fmaf(a3, b[jj], acc[3][j]);
        }
    }
}

// ---------------------------------------------------------------------------
// P = x @ W1[0:128,:] + b1   (M=50000, K=128, N=256)
__global__ void p_kernel(const float* __restrict__ x,
                         const float* __restrict__ W1,
                         const float* __restrict__ b1) {
    __shared__ float As[16 * 65];
    __shared__ float Bs[16 * 256];
    const int m0 = blockIdx.x * 64;
    const int tid = threadIdx.x;
    const int cx = tid & 15, ry = tid >> 4;
    const int ry4 = ry * 4, cn = cx * 16;
    const int lr = tid >> 2, kq = (tid & 3) * 4;
    const int bk = tid >> 4, bn = (tid & 15) * 16;

    float acc[4][16];
#pragma unroll
    for (int i = 0; i < 4; i++)
#pragma unroll
        for (int j = 0; j < 16; j++) acc[i][j] = 0.f;

    for (int kb = 0; kb < NF; kb += 16) {
        int gm = m0 + lr;
        float4 av = make_float4(0.f, 0.f, 0.f, 0.f);
        if (gm < NN) av = *(const float4*)&x[gm * NF + kb + kq];
        As[(kq + 0) * 65 + lr] = av.x;
        As[(kq + 1) * 65 + lr] = av.y;
        As[(kq + 2) * 65 + lr] = av.z;
        As[(kq + 3) * 65 + lr] = av.w;
        const float* wsrc = &W1[(kb + bk) * HID + bn];
#pragma unroll
        for (int j4 = 0; j4 < 4; j4++)
            *(float4*)&Bs[bk * 256 + bn + 4 * j4] = *(const float4*)(wsrc + 4 * j4);
        __syncthreads();
#pragma unroll
        for (int k = 0; k < 16; k++) {
            float a0 = As[k * 65 + ry4 + 0];
            float a1 = As[k * 65 + ry4 + 1];
            float a2 = As[k * 65 + ry4 + 2];
            float a3 = As[k * 65 + ry4 + 3];
            fma_step4(a0, a1, a2, a3, &Bs[k * 256 + cn], acc);
        }
        __syncthreads();
    }

    float bb[16];
#pragma unroll
    for (int j4 = 0; j4 < 4; j4++) {
        float4 v = *(const float4*)&b1[cn + 4 * j4];
        bb[j4 * 4 + 0] = v.x; bb[j4 * 4 + 1] = v.y;
        bb[j4 * 4 + 2] = v.z; bb[j4 * 4 + 3] = v.w;
    }
#pragma unroll
    for (int i = 0; i < 4; i++) {
        int m = m0 + ry4 + i;
        if (m < NN) {
            float* dst = &g_P[m * HID + cn];
#pragma unroll
            for (int j = 0; j < 16; j++) dst[j] = acc[i][j] + bb[j];
        }
    }
}

// ---------------------------------------------------------------------------
// Fused edge MLP: g = edge_attr @ W1[128:,:] + P[row];  h = relu(g) @ W2 + b2
// then atomicAdd into g_agg[col], g_cnt[col]
__global__ void edge_kernel(const float* __restrict__ ea,
                            const void* __restrict__ ei,
                            const float* __restrict__ W1,
                            const float* __restrict__ W2,
                            const float* __restrict__ b2) {
    extern __shared__ float sm[];
    float* Hs = sm;                       // 64 * 260
    float* Bs = sm + 64 * 260;            // 16 * 256
    float* As = Bs + 16 * 256;            // 16 * 65
    int*   rs = (int*)(As + 16 * 65);     // 64
    int*   cs = rs + 64;                  // 64

    const int e0 = blockIdx.x * 64;
    const int tid = threadIdx.x;
    if (tid < 64) {
        rs[tid] = load_index(ei, e0 + tid);
        cs[tid] = load_index(ei, (long long)NE + e0 + tid);
    }
    const int cx = tid & 15, ry = tid >> 4;
    const int ry4 = ry * 4, cn = cx * 16;
    const int lr = tid >> 2, kq = (tid & 3) * 4;
    const int bk = tid >> 4, bn = (tid & 15) * 16;
    const float* W1b = W1 + NF * HID;

    float acc[4][16];
#pragma unroll
    for (int i = 0; i < 4; i++)
#pragma unroll
        for (int j = 0; j < 16; j++) acc[i][j] = 0.f;
    __syncthreads();

    // GEMM1: edge_attr(64x128) @ W1b(128x256)
    for (int kb = 0; kb < NF; kb += 16) {
        float4 av = *(const float4*)&ea[(long long)(e0 + lr) * NF + kb + kq];
        As[(kq + 0) * 65 + lr] = av.x;
        As[(kq + 1) * 65 + lr] = av.y;
        As[(kq + 2) * 65 + lr] = av.z;
        As[(kq + 3) * 65 + lr] = av.w;
        const float* wsrc = &W1b[(kb + bk) * HID + bn];
#pragma unroll
        for (int j4 = 0; j4 < 4; j4++)
            *(float4*)&Bs[bk * 256 + bn + 4 * j4] = *(const float4*)(wsrc + 4 * j4);
        __syncthreads();
#pragma unroll
        for (int k = 0; k < 16; k++) {
            float a0 = As[k * 65 + ry4 + 0];
            float a1 = As[k * 65 + ry4 + 1];
            float a2 = As[k * 65 + ry4 + 2];
            float a3 = As[k * 65 + ry4 + 3];
            fma_step4(a0, a1, a2, a3, &Bs[k * 256 + cn], acc);
        }
        __syncthreads();
    }

    // + P[row] (L2-resident gather), relu, stash h in smem
#pragma unroll
    for (int i = 0; i < 4; i++) {
        const float* Pr = &g_P[(long long)rs[ry4 + i] * HID + cn];
        float* hd = &Hs[(ry4 + i) * 260 + cn];
#pragma unroll
        for (int j4 = 0; j4 < 4; j4++) {
            float4 pv = *(const float4*)(Pr + 4 * j4);
            float4 hv;
            hv.x = fmaxf(acc[i][j4 * 4 + 0] + pv.x, 0.f);
            hv.y = fmaxf(acc[i][j4 * 4 + 1] + pv.y, 0.f);
            hv.z = fmaxf(acc[i][j4 * 4 + 2] + pv.z, 0.f);
            hv.w = fmaxf(acc[i][j4 * 4 + 3] + pv.w, 0.f);
            *(float4*)(hd + 4 * j4) = hv;
        }
    }
#pragma unroll
    for (int i = 0; i < 4; i++)
#pragma unroll
        for (int j = 0; j < 16; j++) acc[i][j] = 0.f;
    __syncthreads();

    // GEMM2: h(64x256) @ W2(256x256)
    for (int kb = 0; kb < HID; kb += 16) {
        const float* wsrc = &W2[(kb + bk) * HID + bn];
#pragma unroll
        for (int j4 = 0; j4 < 4; j4++)
            *(float4*)&Bs[bk * 256 + bn + 4 * j4] = *(const float4*)(wsrc + 4 * j4);
        __syncthreads();
#pragma unroll
        for (int k = 0; k < 16; k++) {
            float a0 = Hs[(ry4 + 0) * 260 + kb + k];
            float a1 = Hs[(ry4 + 1) * 260 + kb + k];
            float a2 = Hs[(ry4 + 2) * 260 + kb + k];
            float a3 = Hs[(ry4 + 3) * 260 + kb + k];
            fma_step4(a0, a1, a2, a3, &Bs[k * 256 + cn], acc);
        }
        __syncthreads();
    }

    float bb[16];
#pragma unroll
    for (int j4 = 0; j4 < 4; j4++) {
        float4 v = *(const float4*)&b2[cn + 4 * j4];
        bb[j4 * 4 + 0] = v.x; bb[j4 * 4 + 1] = v.y;
        bb[j4 * 4 + 2] = v.z; bb[j4 * 4 + 3] = v.w;
    }
#pragma unroll
    for (int i = 0; i < 4; i++) {
        float* dst = &g_agg[(long long)cs[ry4 + i] * HID + cn];
#pragma unroll
        for (int j = 0; j < 16; j++) atomicAdd(dst + j, acc[i][j] + bb[j]);
    }
    if (tid < 64) atomicAdd(&g_cnt[cs[tid]], 1.0f);
}

// ---------------------------------------------------------------------------
// Fused node MLP: z=[x || agg/cnt || u[batch]] (448) @W3 +b3, relu, @W4 +b4
__global__ void node_kernel(const float* __restrict__ x,
                            const float* __restrict__ u,
                            const void* __restrict__ batch,
                            const float* __restrict__ W3,
                            const float* __restrict__ b3,
                            const float* __restrict__ W4,
                            const float* __restrict__ b4,
                            float* __restrict__ out) {
    extern __shared__ float sm[];
    float* Ts = sm;                       // 64 * 260
    float* Bs = sm + 64 * 260;            // 16 * 256
    float* As = Bs + 16 * 256;            // 16 * 65
    int*   bt = (int*)(As + 16 * 65);     // 64
    float* rc = (float*)(bt + 64);        // 64

    const int m0 = blockIdx.x * 64;
    const int tid = threadIdx.x;
    if (tid < 64) {
        int n = m0 + tid;
        if (n < NN) {
            int b = load_index(batch, n);
            bt[tid] = (b < 64) ? b : 0;
            rc[tid] = 1.0f / fmaxf(g_cnt[n], 1.0f);
        } else {
            bt[tid] = 0;
            rc[tid] = 0.f;
        }
    }
    __syncthreads();

    const int cx = tid & 15, ry = tid >> 4;
    const int ry4 = ry * 4, cn = cx * 16;
    const int lr = tid >> 2, kq = (tid & 3) * 4;
    const int bk = tid >> 4, bn = (tid & 15) * 16;

    float acc[4][16];
#pragma unroll
    for (int i = 0; i < 4; i++)
#pragma unroll
        for (int j = 0; j < 16; j++) acc[i][j] = 0.f;

    // GEMM1: z(64x448) @ W3(448x256), z assembled on the fly
    for (int kb = 0; kb < NF + HID + UF; kb += 16) {
        int n = m0 + lr;
        int k = kb + kq;
        float4 av = make_float4(0.f, 0.f, 0.f, 0.f);
        if (n < NN) {
            if (k < NF) {
                av = *(const float4*)&x[(long long)n * NF + k];
            } else if (k < NF + HID) {
                av = *(const float4*)&g_agg[(long long)n * HID + (k - NF)];
                float r = rc[lr];
                av.x *= r; av.y *= r; av.z *= r; av.w *= r;
            } else {
                av = *(const float4*)&u[bt[lr] * UF + (k - NF - HID)];
            }
        }
        As[(kq + 0) * 65 + lr] = av.x;
        As[(kq + 1) * 65 + lr] = av.y;
        As[(kq + 2) * 65 + lr] = av.z;
        As[(kq + 3) * 65 + lr] = av.w;
        const float* wsrc = &W3[(kb + bk) * HID + bn];
#pragma unroll
        for (int j4 = 0; j4 < 4; j4++)
            *(float4*)&Bs[bk * 256 + bn + 4 * j4] = *(const float4*)(wsrc + 4 * j4);
        __syncthreads();
#pragma unroll
        for (int k2 = 0; k2 < 16; k2++) {
            float a0 = As[k2 * 65 + ry4 + 0];
            float a1 = As[k2 * 65 + ry4 + 1];
            float a2 = As[k2 * 65 + ry4 + 2];
            float a3 = As[k2 * 65 + ry4 + 3];
            fma_step4(a0, a1, a2, a3, &Bs[k2 * 256 + cn], acc);
        }
        __syncthreads();
    }

    // relu(+b3) -> Ts
    float bb[16];
#pragma unroll
    for (int j4 = 0; j4 < 4; j4++) {
        float4 v = *(const float4*)&b3[cn + 4 * j4];
        bb[j4 * 4 + 0] = v.x; bb[j4 * 4 + 1] = v.y;
        bb[j4 * 4 + 2] = v.z; bb[j4 * 4 + 3] = v.w;
    }
#pragma unroll
    for (int i = 0; i < 4; i++) {
        float* td = &Ts[(ry4 + i) * 260 + cn];
#pragma unroll
        for (int j4 = 0; j4 < 4; j4++) {
            float4 tv;
            tv.x = fmaxf(acc[i][j4 * 4 + 0] + bb[j4 * 4 + 0], 0.f);
            tv.y = fmaxf(acc[i][j4 * 4 + 1] + bb[j4 * 4 + 1], 0.f);
            tv.z = fmaxf(acc[i][j4 * 4 + 2] + bb[j4 * 4 + 2], 0.f);
            tv.w = fmaxf(acc[i][j4 * 4 + 3] + bb[j4 * 4 + 3], 0.f);
            *(float4*)(td + 4 * j4) = tv;
        }
    }
    __syncthreads();

    // GEMM2: t(64x256) @ W4(256x128); remap: 2 rows x 16 cols per thread
    const int cx2 = tid & 7, ry2 = tid >> 3;
    const int cn2 = cx2 * 16, rr = ry2 * 2;
    const int bk2 = tid >> 4, bn2 = (tid & 15) * 8;
    float acc2[2][16];
#pragma unroll
    for (int i = 0; i < 2; i++)
#pragma unroll
        for (int j = 0; j < 16; j++) acc2[i][j] = 0.f;

    for (int kb = 0; kb < HID; kb += 16) {
        const float* wsrc = &W4[(kb + bk2) * NF + bn2];
        *(float4*)&Bs[bk2 * 128 + bn2]     = *(const float4*)wsrc;
        *(float4*)&Bs[bk2 * 128 + bn2 + 4] = *(const float4*)(wsrc + 4);
        __syncthreads();
#pragma unroll
        for (int k = 0; k < 16; k++) {
            float a0 = Ts[(rr + 0) * 260 + kb + k];
            float a1 = Ts[(rr + 1) * 260 + kb + k];
            const float* bp = &Bs[k * 128 + cn2];
#pragma unroll
            for (int j4 = 0; j4 < 4; j4++) {
                float4 bv = *(const float4*)(bp + 4 * j4);
                float b[4] = {bv.x, bv.y, bv.z, bv.w};
#pragma unroll
                for (int jj = 0; jj < 4; jj++) {
                    int j = j4 * 4 + jj;
                    acc2[0][j] = fmaf(a0, b[jj], acc2[0][j]);
                    acc2[1][j] = fmaf(a1, b[jj], acc2[1][j]);
                }
            }
        }
        __syncthreads();
    }

    float b4v[16];
#pragma unroll
    for (int j4 = 0; j4 < 4; j4++) {
        float4 v = *(const float4*)&b4[cn2 + 4 * j4];
        b4v[j4 * 4 + 0] = v.x; b4v[j4 * 4 + 1] = v.y;
        b4v[j4 * 4 + 2] = v.z; b4v[j4 * 4 + 3] = v.w;
    }
#pragma unroll
    for (int i = 0; i < 2; i++) {
        int n = m0 + rr + i;
        if (n < NN) {
            float* dst = &out[(long long)n * NF + cn2];
#pragma unroll
            for (int j = 0; j < 16; j++) dst[j] = acc2[i][j] + b4v[j];
        }
    }
}

// ---------------------------------------------------------------------------
extern "C" void kernel_launch(void* const* d_in, const int* in_sizes, int n_in,
                              void* d_out, int out_size) {
    const float* x     = (const float*)d_in[0];
    const void*  ei    = d_in[1];
    const float* ea    = (const float*)d_in[2];
    const float* u     = (const float*)d_in[3];
    const void*  batch = d_in[4];
    const float* W1    = (const float*)d_in[5];
    const float* b1    = (const float*)d_in[6];
    const float* W2    = (const float*)d_in[7];
    const float* b2    = (const float*)d_in[8];
    const float* W3    = (const float*)d_in[9];
    const float* b3    = (const float*)d_in[10];
    const float* W4    = (const float*)d_in[11];
    const float* b4    = (const float*)d_in[12];
    float* out = (float*)d_out;

    const int EDGE_SMEM = (64 * 260 + 16 * 256 + 16 * 65) * 4 + 128 * 2 * 4;
    const int NODE_SMEM = (64 * 260 + 16 * 256 + 16 * 65) * 4 + 64 * 2 * 4;
    static int attr_done = 0;
    if (!attr_done) {
        cudaFuncSetAttribute(edge_kernel, cudaFuncAttributeMaxDynamicSharedMemorySize, EDGE_SMEM);
        cudaFuncSetAttribute(node_kernel, cudaFuncAttributeMaxDynamicSharedMemorySize, NODE_SMEM);
        attr_done = 1;
    }

    zero_kernel<<<2048, 256>>>(ei);
    p_kernel<<<(NN + 63) / 64, 256>>>(x, W1, b1);
    edge_kernel<<<NE / 64, 256, EDGE_SMEM>>>(ea, ei, W1, W2, b2);
    node_kernel<<<(NN + 63) / 64, 256, NODE_SMEM>>>(x, u, batch, W3, b3, W4, b4, out);
}

// round 6
// speedup vs baseline: 1.8447x; 1.8447x over previous
#include <cuda_runtime.h>

#define NN   50000
#define NE   640000
#define NF   128
#define HID  256
#define UF   64

__device__ float g_P[NN * HID];     // x @ W1[:128] + b1, per node
__device__ float g_agg[NN * HID];   // scatter-sum of relu(g)
__device__ float g_hagg[NN * HID];  // mean(relu g) @ W2 + b2*[cnt>0]
__device__ float g_cnt[NN];
__device__ int   g_is64;

// ---------------------------------------------------------------------------
__global__ void zero_kernel(const void* ei_raw) {
    int idx = blockIdx.x * blockDim.x + threadIdx.x;
    int stride = gridDim.x * blockDim.x;
    for (int i = idx; i < NN * HID; i += stride) g_agg[i] = 0.f;
    for (int i = idx; i < NN; i += stride) g_cnt[i] = 0.f;
    if (blockIdx.x == 0 && threadIdx.x == 0) {
        const long long* p = (const long long*)ei_raw;
        int ok = 1;
        for (int i = 0; i < 1024; i++) {
            long long v = p[i];
            if (v < 0 || v >= NN) { ok = 0; break; }
        }
        g_is64 = ok;
    }
}

__device__ __forceinline__ int load_index(const void* p, long long i) {
    long long v = g_is64 ? ((const long long*)p)[i] : (long long)((const int*)p)[i];
    if (v < 0) v = 0;
    if (v >= NN) v = NN - 1;
    return (int)v;
}

// ---------------------------------------------------------------------------
__device__ __forceinline__ void fma_step4(float a0, float a1, float a2, float a3,
                                          const float* __restrict__ bp,
                                          float acc[4][16]) {
#pragma unroll
    for (int j4 = 0; j4 < 4; j4++) {
        float4 bv = *(const float4*)(bp + 4 * j4);
        float b[4] = {bv.x, bv.y, bv.z, bv.w};
#pragma unroll
        for (int jj = 0; jj < 4; jj++) {
            int j = j4 * 4 + jj;
            acc[0][j] = fmaf(a0, b[jj], acc[0][j]);
            acc[1][j] = fmaf(a1, b[jj], acc[1][j]);
            acc[2][j] = fmaf(a2, b[jj], acc[2][j]);
            acc[3][j] = fmaf(a3, b[jj], acc[3][j]);
        }
    }
}

// ---------------------------------------------------------------------------
// P = x @ W1[0:128,:] + b1   (M=50000, K=128, N=256)
__global__ void p_kernel(const float* __restrict__ x,
                         const float* __restrict__ W1,
                         const float* __restrict__ b1) {
    __shared__ float As[16 * 65];
    __shared__ float Bs[16 * 256];
    const int m0 = blockIdx.x * 64;
    const int tid = threadIdx.x;
    const int cx = tid & 15, ry = tid >> 4;
    const int ry4 = ry * 4, cn = cx * 16;
    const int lr = tid >> 2, kq = (tid & 3) * 4;
    const int bk = tid >> 4, bn = (tid & 15) * 16;

    float acc[4][16];
#pragma unroll
    for (int i = 0; i < 4; i++)
#pragma unroll
        for (int j = 0; j < 16; j++) acc[i][j] = 0.f;

    for (int kb = 0; kb < NF; kb += 16) {
        int gm = m0 + lr;
        float4 av = make_float4(0.f, 0.f, 0.f, 0.f);
        if (gm < NN) av = *(const float4*)&x[(long long)gm * NF + kb + kq];
        As[(kq + 0) * 65 + lr] = av.x;
        As[(kq + 1) * 65 + lr] = av.y;
        As[(kq + 2) * 65 + lr] = av.z;
        As[(kq + 3) * 65 + lr] = av.w;
        const float* wsrc = &W1[(kb + bk) * HID + bn];
#pragma unroll
        for (int j4 = 0; j4 < 4; j4++)
            *(float4*)&Bs[bk * 256 + bn + 4 * j4] = *(const float4*)(wsrc + 4 * j4);
        __syncthreads();
#pragma unroll
        for (int k = 0; k < 16; k++) {
            float a0 = As[k * 65 + ry4 + 0];
            float a1 = As[k * 65 + ry4 + 1];
            float a2 = As[k * 65 + ry4 + 2];
            float a3 = As[k * 65 + ry4 + 3];
            fma_step4(a0, a1, a2, a3, &Bs[k * 256 + cn], acc);
        }
        __syncthreads();
    }

    float bb[16];
#pragma unroll
    for (int j4 = 0; j4 < 4; j4++) {
        float4 v = *(const float4*)&b1[cn + 4 * j4];
        bb[j4 * 4 + 0] = v.x; bb[j4 * 4 + 1] = v.y;
        bb[j4 * 4 + 2] = v.z; bb[j4 * 4 + 3] = v.w;
    }
#pragma unroll
    for (int i = 0; i < 4; i++) {
        int m = m0 + ry4 + i;
        if (m < NN) {
            float* dst = &g_P[(long long)m * HID + cn];
#pragma unroll
            for (int j = 0; j < 16; j++) dst[j] = acc[i][j] + bb[j];
        }
    }
}

// ---------------------------------------------------------------------------
// Edge: g = edge_attr @ W1[128:,:] + P[row]; scatter relu(g) into g_agg[col]
// (W2 commuted through scatter_mean; applied per-node in agg2_kernel)
__global__ void edge_kernel(const float* __restrict__ ea,
                            const void* __restrict__ ei,
                            const float* __restrict__ W1) {
    __shared__ float As[16 * 65];
    __shared__ float Bs[16 * 256];
    __shared__ int rs[64], cs[64];

    const int e0 = blockIdx.x * 64;
    const int tid = threadIdx.x;
    if (tid < 64) {
        rs[tid] = load_index(ei, e0 + tid);
        cs[tid] = load_index(ei, (long long)NE + e0 + tid);
    }
    const int cx = tid & 15, ry = tid >> 4;
    const int ry4 = ry * 4, cn = cx * 16;
    const int lr = tid >> 2, kq = (tid & 3) * 4;
    const int bk = tid >> 4, bn = (tid & 15) * 16;
    const float* W1b = W1 + NF * HID;

    float acc[4][16];
#pragma unroll
    for (int i = 0; i < 4; i++)
#pragma unroll
        for (int j = 0; j < 16; j++) acc[i][j] = 0.f;
    __syncthreads();

    for (int kb = 0; kb < NF; kb += 16) {
        float4 av = *(const float4*)&ea[(long long)(e0 + lr) * NF + kb + kq];
        As[(kq + 0) * 65 + lr] = av.x;
        As[(kq + 1) * 65 + lr] = av.y;
        As[(kq + 2) * 65 + lr] = av.z;
        As[(kq + 3) * 65 + lr] = av.w;
        const float* wsrc = &W1b[(kb + bk) * HID + bn];
#pragma unroll
        for (int j4 = 0; j4 < 4; j4++)
            *(float4*)&Bs[bk * 256 + bn + 4 * j4] = *(const float4*)(wsrc + 4 * j4);
        __syncthreads();
#pragma unroll
        for (int k = 0; k < 16; k++) {
            float a0 = As[k * 65 + ry4 + 0];
            float a1 = As[k * 65 + ry4 + 1];
            float a2 = As[k * 65 + ry4 + 2];
            float a3 = As[k * 65 + ry4 + 3];
            fma_step4(a0, a1, a2, a3, &Bs[k * 256 + cn], acc);
        }
        __syncthreads();
    }

    // + P[row], relu, scatter
#pragma unroll
    for (int i = 0; i < 4; i++) {
        const float* Pr = &g_P[(long long)rs[ry4 + i] * HID + cn];
        float* dst = &g_agg[(long long)cs[ry4 + i] * HID + cn];
#pragma unroll
        for (int j4 = 0; j4 < 4; j4++) {
            float4 pv = *(const float4*)(Pr + 4 * j4);
            atomicAdd(dst + 4 * j4 + 0, fmaxf(acc[i][j4 * 4 + 0] + pv.x, 0.f));
            atomicAdd(dst + 4 * j4 + 1, fmaxf(acc[i][j4 * 4 + 1] + pv.y, 0.f));
            atomicAdd(dst + 4 * j4 + 2, fmaxf(acc[i][j4 * 4 + 2] + pv.z, 0.f));
            atomicAdd(dst + 4 * j4 + 3, fmaxf(acc[i][j4 * 4 + 3] + pv.w, 0.f));
        }
    }
    if (tid < 64) atomicAdd(&g_cnt[cs[tid]], 1.0f);
}

// ---------------------------------------------------------------------------
// agg2: g_hagg = (g_agg / max(cnt,1)) @ W2 + b2*[cnt>0]   (per-node, 50K rows)
__global__ void agg2_kernel(const float* __restrict__ W2,
                            const float* __restrict__ b2) {
    __shared__ float As[16 * 65];
    __shared__ float Bs[16 * 256];
    __shared__ float rcs[64];
    __shared__ float inds[64];
    const int m0 = blockIdx.x * 64;
    const int tid = threadIdx.x;
    if (tid < 64) {
        int n = m0 + tid;
        float c = (n < NN) ? g_cnt[n] : 0.f;
        rcs[tid] = 1.0f / fmaxf(c, 1.0f);
        inds[tid] = (c > 0.f) ? 1.0f : 0.f;
    }
    const int cx = tid & 15, ry = tid >> 4;
    const int ry4 = ry * 4, cn = cx * 16;
    const int lr = tid >> 2, kq = (tid & 3) * 4;
    const int bk = tid >> 4, bn = (tid & 15) * 16;

    float acc[4][16];
#pragma unroll
    for (int i = 0; i < 4; i++)
#pragma unroll
        for (int j = 0; j < 16; j++) acc[i][j] = 0.f;
    __syncthreads();

    for (int kb = 0; kb < HID; kb += 16) {
        int gm = m0 + lr;
        float4 av = make_float4(0.f, 0.f, 0.f, 0.f);
        if (gm < NN) {
            av = *(const float4*)&g_agg[(long long)gm * HID + kb + kq];
            float r = rcs[lr];
            av.x *= r; av.y *= r; av.z *= r; av.w *= r;
        }
        As[(kq + 0) * 65 + lr] = av.x;
        As[(kq + 1) * 65 + lr] = av.y;
        As[(kq + 2) * 65 + lr] = av.z;
        As[(kq + 3) * 65 + lr] = av.w;
        const float* wsrc = &W2[(kb + bk) * HID + bn];
#pragma unroll
        for (int j4 = 0; j4 < 4; j4++)
            *(float4*)&Bs[bk * 256 + bn + 4 * j4] = *(const float4*)(wsrc + 4 * j4);
        __syncthreads();
#pragma unroll
        for (int k = 0; k < 16; k++) {
            float a0 = As[k * 65 + ry4 + 0];
            float a1 = As[k * 65 + ry4 + 1];
            float a2 = As[k * 65 + ry4 + 2];
            float a3 = As[k * 65 + ry4 + 3];
            fma_step4(a0, a1, a2, a3, &Bs[k * 256 + cn], acc);
        }
        __syncthreads();
    }

    float bb[16];
#pragma unroll
    for (int j4 = 0; j4 < 4; j4++) {
        float4 v = *(const float4*)&b2[cn + 4 * j4];
        bb[j4 * 4 + 0] = v.x; bb[j4 * 4 + 1] = v.y;
        bb[j4 * 4 + 2] = v.z; bb[j4 * 4 + 3] = v.w;
    }
#pragma unroll
    for (int i = 0; i < 4; i++) {
        int m = m0 + ry4 + i;
        if (m < NN) {
            float ind = inds[ry4 + i];
            float* dst = &g_hagg[(long long)m * HID + cn];
#pragma unroll
            for (int j = 0; j < 16; j++) dst[j] = acc[i][j] + bb[j] * ind;
        }
    }
}

// ---------------------------------------------------------------------------
// Node MLP: z=[x || hagg || u[batch]] (448) @W3 +b3, relu, @W4 +b4
__global__ void node_kernel(const float* __restrict__ x,
                            const float* __restrict__ u,
                            const void* __restrict__ batch,
                            const float* __restrict__ W3,
                            const float* __restrict__ b3,
                            const float* __restrict__ W4,
                            const float* __restrict__ b4,
                            float* __restrict__ out) {
    extern __shared__ float sm[];
    float* Ts = sm;                       // 64 * 260
    float* Bs = sm + 64 * 260;            // 16 * 256
    float* As = Bs + 16 * 256;            // 16 * 65
    int*   bt = (int*)(As + 16 * 65);     // 64

    const int m0 = blockIdx.x * 64;
    const int tid = threadIdx.x;
    if (tid < 64) {
        int n = m0 + tid;
        int b = (n < NN) ? load_index(batch, n) : 0;
        bt[tid] = (b < 64) ? b : 0;
    }
    __syncthreads();

    const int cx = tid & 15, ry = tid >> 4;
    const int ry4 = ry * 4, cn = cx * 16;
    const int lr = tid >> 2, kq = (tid & 3) * 4;
    const int bk = tid >> 4, bn = (tid & 15) * 16;

    float acc[4][16];
#pragma unroll
    for (int i = 0; i < 4; i++)
#pragma unroll
        for (int j = 0; j < 16; j++) acc[i][j] = 0.f;

    for (int kb = 0; kb < NF + HID + UF; kb += 16) {
        int n = m0 + lr;
        int k = kb + kq;
        float4 av = make_float4(0.f, 0.f, 0.f, 0.f);
        if (n < NN) {
            if (k < NF) {
                av = *(const float4*)&x[(long long)n * NF + k];
            } else if (k < NF + HID) {
                av = *(const float4*)&g_hagg[(long long)n * HID + (k - NF)];
            } else {
                av = *(const float4*)&u[bt[lr] * UF + (k - NF - HID)];
            }
        }
        As[(kq + 0) * 65 + lr] = av.x;
        As[(kq + 1) * 65 + lr] = av.y;
        As[(kq + 2) * 65 + lr] = av.z;
        As[(kq + 3) * 65 + lr] = av.w;
        const float* wsrc = &W3[(kb + bk) * HID + bn];
#pragma unroll
        for (int j4 = 0; j4 < 4; j4++)
            *(float4*)&Bs[bk * 256 + bn + 4 * j4] = *(const float4*)(wsrc + 4 * j4);
        __syncthreads();
#pragma unroll
        for (int k2 = 0; k2 < 16; k2++) {
            float a0 = As[k2 * 65 + ry4 + 0];
            float a1 = As[k2 * 65 + ry4 + 1];
            float a2 = As[k2 * 65 + ry4 + 2];
            float a3 = As[k2 * 65 + ry4 + 3];
            fma_step4(a0, a1, a2, a3, &Bs[k2 * 256 + cn], acc);
        }
        __syncthreads();
    }

    float bb[16];
#pragma unroll
    for (int j4 = 0; j4 < 4; j4++) {
        float4 v = *(const float4*)&b3[cn + 4 * j4];
        bb[j4 * 4 + 0] = v.x; bb[j4 * 4 + 1] = v.y;
        bb[j4 * 4 + 2] = v.z; bb[j4 * 4 + 3] = v.w;
    }
#pragma unroll
    for (int i = 0; i < 4; i++) {
        float* td = &Ts[(ry4 + i) * 260 + cn];
#pragma unroll
        for (int j4 = 0; j4 < 4; j4++) {
            float4 tv;
            tv.x = fmaxf(acc[i][j4 * 4 + 0] + bb[j4 * 4 + 0], 0.f);
            tv.y = fmaxf(acc[i][j4 * 4 + 1] + bb[j4 * 4 + 1], 0.f);
            tv.z = fmaxf(acc[i][j4 * 4 + 2] + bb[j4 * 4 + 2], 0.f);
            tv.w = fmaxf(acc[i][j4 * 4 + 3] + bb[j4 * 4 + 3], 0.f);
            *(float4*)(td + 4 * j4) = tv;
        }
    }
    __syncthreads();

    // GEMM2: t(64x256) @ W4(256x128)
    const int cx2 = tid & 7, ry2 = tid >> 3;
    const int cn2 = cx2 * 16, rr = ry2 * 2;
    const int bk2 = tid >> 4, bn2 = (tid & 15) * 8;
    float acc2[2][16];
#pragma unroll
    for (int i = 0; i < 2; i++)
#pragma unroll
        for (int j = 0; j < 16; j++) acc2[i][j] = 0.f;

    for (int kb = 0; kb < HID; kb += 16) {
        const float* wsrc = &W4[(kb + bk2) * NF + bn2];
        *(float4*)&Bs[bk2 * 128 + bn2]     = *(const float4*)wsrc;
        *(float4*)&Bs[bk2 * 128 + bn2 + 4] = *(const float4*)(wsrc + 4);
        __syncthreads();
#pragma unroll
        for (int k = 0; k < 16; k++) {
            float a0 = Ts[(rr + 0) * 260 + kb + k];
            float a1 = Ts[(rr + 1) * 260 + kb + k];
            const float* bp = &Bs[k * 128 + cn2];
#pragma unroll
            for (int j4 = 0; j4 < 4; j4++) {
                float4 bv = *(const float4*)(bp + 4 * j4);
                float b[4] = {bv.x, bv.y, bv.z, bv.w};
#pragma unroll
                for (int jj = 0; jj < 4; jj++) {
                    int j = j4 * 4 + jj;
                    acc2[0][j] = fmaf(a0, b[jj], acc2[0][j]);
                    acc2[1][j] = fmaf(a1, b[jj], acc2[1][j]);
                }
            }
        }
        __syncthreads();
    }

    float b4v[16];
#pragma unroll
    for (int j4 = 0; j4 < 4; j4++) {
        float4 v = *(const float4*)&b4[cn2 + 4 * j4];
        b4v[j4 * 4 + 0] = v.x; b4v[j4 * 4 + 1] = v.y;
        b4v[j4 * 4 + 2] = v.z; b4v[j4 * 4 + 3] = v.w;
    }
#pragma unroll
    for (int i = 0; i < 2; i++) {
        int n = m0 + rr + i;
        if (n < NN) {
            float* dst = &out[(long long)n * NF + cn2];
#pragma unroll
            for (int j = 0; j < 16; j++) dst[j] = acc2[i][j] + b4v[j];
        }
    }
}

// ---------------------------------------------------------------------------
extern "C" void kernel_launch(void* const* d_in, const int* in_sizes, int n_in,
                              void* d_out, int out_size) {
    const float* x     = (const float*)d_in[0];
    const void*  ei    = d_in[1];
    const float* ea    = (const float*)d_in[2];
    const float* u     = (const float*)d_in[3];
    const void*  batch = d_in[4];
    const float* W1    = (const float*)d_in[5];
    const float* b1    = (const float*)d_in[6];
    const float* W2    = (const float*)d_in[7];
    const float* b2    = (const float*)d_in[8];
    const float* W3    = (const float*)d_in[9];
    const float* b3    = (const float*)d_in[10];
    const float* W4    = (const float*)d_in[11];
    const float* b4    = (const float*)d_in[12];
    float* out = (float*)d_out;

    const int NODE_SMEM = (64 * 260 + 16 * 256 + 16 * 65) * 4 + 64 * 4;
    static int attr_done = 0;
    if (!attr_done) {
        cudaFuncSetAttribute(node_kernel, cudaFuncAttributeMaxDynamicSharedMemorySize, NODE_SMEM);
        attr_done = 1;
    }

    zero_kernel<<<2048, 256>>>(ei);
    p_kernel<<<(NN + 63) / 64, 256>>>(x, W1, b1);
    edge_kernel<<<NE / 64, 256>>>(ea, ei, W1);
    agg2_kernel<<<(NN + 63) / 64, 256>>>(W2, b2);
    node_kernel<<<(NN + 63) / 64, 256, NODE_SMEM>>>(x, u, batch, W3, b3, W4, b4, out);
}

// round 9
// speedup vs baseline: 3.9038x; 2.1162x over previous
#include <cuda_runtime.h>
#include <cuda_bf16.h>
#include <mma.h>
#include <cstdint>

using namespace nvcuda;

#define NN   50000
#define NE   640000
#define HID  256
#define LD   80          // smem leading dim (elements) for A/B staging

// transposed [N][K] bf16 weight store; hi at +0, lo at +WB_HALF
#define WOF_W1A 0
#define WOF_W1B 32768
#define WOF_W2  65536
#define WOF_W3  131072
#define WOF_W4  245760
#define WB_HALF 278528

__device__ __align__(16) __nv_bfloat16 g_wb[2 * WB_HALF];
__device__ float g_P[NN * HID];      // P = x@W1a+b1; later reused as t-scratch
__device__ float g_agg[NN * HID];    // scatter-sum of relu(g)
__device__ float g_hagg[NN * HID];   // mean @ W2 + b2*ind
__device__ float g_cnt[NN];
__device__ int   g_is64;

#define SMEM_TOTAL (4 * 128 * LD * 2)   // Ah, Al, Bh, Bl bf16 buffers = 81920 B

// ---------------------------------------------------------------------------
__global__ void zero_kernel(const void* ei_raw) {
    int idx = blockIdx.x * blockDim.x + threadIdx.x;
    int stride = gridDim.x * blockDim.x;
    for (int i = idx; i < NN * HID; i += stride) g_agg[i] = 0.f;
    for (int i = idx; i < NN; i += stride) g_cnt[i] = 0.f;
    if (idx == 0) {
        const long long* p = (const long long*)ei_raw;
        int ok = 1;
        for (int i = 0; i < 1024; i++) {
            long long v = p[i];
            if (v < 0 || v >= NN) { ok = 0; break; }
        }
        g_is64 = ok;
    }
}

__device__ __forceinline__ int load_index(const void* p, long long i) {
    long long v = g_is64 ? ((const long long*)p)[i] : (long long)((const int*)p)[i];
    if (v < 0) v = 0;
    if (v >= NN) v = NN - 1;
    return (int)v;
}

// prep: weights -> [N][K] bf16 hi/lo
__global__ void prep_kernel(const float* __restrict__ W1, const float* __restrict__ W2,
                            const float* __restrict__ W3, const float* __restrict__ W4) {
    int i = blockIdx.x * blockDim.x + threadIdx.x;
    int stride = gridDim.x * blockDim.x;
    for (; i < WB_HALF; i += stride) {
        float v; int l, n, k;
        if (i < 32768)       { l = i;          n = l >> 7; k = l & 127; v = W1[k * 256 + n]; }
        else if (i < 65536)  { l = i - 32768;  n = l >> 7; k = l & 127; v = W1[(k + 128) * 256 + n]; }
        else if (i < 131072) { l = i - 65536;  n = l >> 8; k = l & 255; v = W2[k * 256 + n]; }
        else if (i < 245760) { l = i - 131072; n = l / 448; k = l % 448; v = W3[k * 256 + n]; }
        else                 { l = i - 245760; n = l >> 8; k = l & 255; v = W4[k * 128 + n]; }
        __nv_bfloat16 h = __float2bfloat16(v);
        g_wb[i] = h;
        g_wb[WB_HALF + i] = __float2bfloat16(v - __bfloat162float(h));
    }
}

// ---------------------------------------------------------------------------
typedef wmma::fragment<wmma::accumulator, 16, 16, 16, float> FragC;

__device__ __forceinline__ void split4(float4 v, __nv_bfloat16* h, __nv_bfloat16* l) {
    float a[4] = {v.x, v.y, v.z, v.w};
#pragma unroll
    for (int i = 0; i < 4; i++) {
        __nv_bfloat16 hi = __float2bfloat16(a[i]);
        h[i] = hi;
        l[i] = __float2bfloat16(a[i] - __bfloat162float(hi));
    }
}

// stage 128 rows x 64 cols of B (hi+lo) from g_wb[NxK] into smem
__device__ __forceinline__ void stage_B(__nv_bfloat16* Bh, __nv_bfloat16* Bl,
                                        int wof, int K, int n0, int kc, int tid) {
    const __nv_bfloat16* sh = g_wb + wof + (size_t)n0 * K + kc;
    const __nv_bfloat16* sl = sh + WB_HALF;
    for (int i = tid; i < 1024; i += 256) {
        int n = i >> 3, kq = (i & 7) * 8;
        *(uint4*)(Bh + n * LD + kq) = *(const uint4*)(sh + (size_t)n * K + kq);
        *(uint4*)(Bl + n * LD + kq) = *(const uint4*)(sl + (size_t)n * K + kq);
    }
}

// one 64-deep K chunk of warp-level MMA (3-term bf16 split)
__device__ __forceinline__ void warp_gemm64(const __nv_bfloat16* Ah, const __nv_bfloat16* Al,
                                            const __nv_bfloat16* Bh, const __nv_bfloat16* Bl,
                                            FragC acc[2][4], int wm, int wn) {
#pragma unroll
    for (int kk = 0; kk < 64; kk += 16) {
        wmma::fragment<wmma::matrix_a, 16, 16, 16, __nv_bfloat16, wmma::row_major> ah[2], al[2];
#pragma unroll
        for (int mi = 0; mi < 2; mi++) {
            wmma::load_matrix_sync(ah[mi], Ah + (wm * 32 + mi * 16) * LD + kk, LD);
            wmma::load_matrix_sync(al[mi], Al + (wm * 32 + mi * 16) * LD + kk, LD);
        }
#pragma unroll
        for (int ni = 0; ni < 4; ni++) {
            wmma::fragment<wmma::matrix_b, 16, 16, 16, __nv_bfloat16, wmma::col_major> bh, bl;
            wmma::load_matrix_sync(bh, Bh + (wn * 64 + ni * 16) * LD + kk, LD);
            wmma::load_matrix_sync(bl, Bl + (wn * 64 + ni * 16) * LD + kk, LD);
#pragma unroll
            for (int mi = 0; mi < 2; mi++) {
                wmma::mma_sync(acc[mi][ni], ah[mi], bh, acc[mi][ni]);
                wmma::mma_sync(acc[mi][ni], al[mi], bh, acc[mi][ni]);
                wmma::mma_sync(acc[mi][ni], ah[mi], bl, acc[mi][ni]);
            }
        }
    }
}

__device__ __forceinline__ void store_C(float* Cs, FragC acc[2][4], int wm, int wn) {
#pragma unroll
    for (int mi = 0; mi < 2; mi++)
#pragma unroll
        for (int ni = 0; ni < 4; ni++)
            wmma::store_matrix_sync(Cs + (wm * 32 + mi * 16) * 128 + wn * 64 + ni * 16,
                                    acc[mi][ni], 128, wmma::mem_row_major);
}

#define GEMM_VARS() \
    extern __shared__ char smem[]; \
    __nv_bfloat16* Ah = (__nv_bfloat16*)smem; \
    __nv_bfloat16* Al = Ah + 128 * LD; \
    __nv_bfloat16* Bh = Al + 128 * LD; \
    __nv_bfloat16* Bl = Bh + 128 * LD; \
    float* Cs = (float*)smem; \
    int tid = threadIdx.x, w = tid >> 5, wm = w >> 1, wn = w & 1; \
    int er = tid >> 1, ec0 = (tid & 1) * 64;

// ------------------------- p: P = x @ W1a + b1 (K=128, N=256) -------------------------
__global__ __launch_bounds__(256, 2) void p_kernel(const float* __restrict__ x,
                                                   const float* __restrict__ b1) {
    GEMM_VARS();
    int m0 = blockIdx.x * 128;
    for (int nc = 0; nc < 2; nc++) {
        FragC acc[2][4];
#pragma unroll
        for (int mi = 0; mi < 2; mi++)
#pragma unroll
            for (int ni = 0; ni < 4; ni++) wmma::fill_fragment(acc[mi][ni], 0.f);
        for (int kc = 0; kc < 128; kc += 64) {
            __syncthreads();
            for (int i = tid; i < 2048; i += 256) {
                int r = i >> 4, q = (i & 15) * 4;
                int n = m0 + r;
                float4 v = (n < NN) ? *(const float4*)&x[(size_t)n * 128 + kc + q]
                                    : make_float4(0.f, 0.f, 0.f, 0.f);
                split4(v, Ah + r * LD + q, Al + r * LD + q);
            }
            stage_B(Bh, Bl, WOF_W1A, 128, nc * 128, kc, tid);
            __syncthreads();
            warp_gemm64(Ah, Al, Bh, Bl, acc, wm, wn);
        }
        __syncthreads();
        store_C(Cs, acc, wm, wn);
        __syncthreads();
        int n = m0 + er;
        if (n < NN) {
            float* dst = &g_P[(size_t)n * HID + nc * 128 + ec0];
            const float* bb = b1 + nc * 128 + ec0;
#pragma unroll
            for (int q = 0; q < 64; q++) dst[q] = Cs[er * 128 + ec0 + q] + __ldg(bb + q);
        }
    }
}

// ------------------------- edge: scatter relu(ea@W1b + P[row]) (K=128, N=256) ----------
__global__ __launch_bounds__(256, 2) void edge_kernel(const float* __restrict__ ea,
                                                      const void* __restrict__ ei) {
    GEMM_VARS();
    __shared__ int rs[128], cs[128];
    int e0 = blockIdx.x * 128;
    if (tid < 128) {
        rs[tid] = load_index(ei, e0 + tid);
        cs[tid] = load_index(ei, (long long)NE + e0 + tid);
    }
    for (int nc = 0; nc < 2; nc++) {
        FragC acc[2][4];
#pragma unroll
        for (int mi = 0; mi < 2; mi++)
#pragma unroll
            for (int ni = 0; ni < 4; ni++) wmma::fill_fragment(acc[mi][ni], 0.f);
        for (int kc = 0; kc < 128; kc += 64) {
            __syncthreads();
            for (int i = tid; i < 2048; i += 256) {
                int r = i >> 4, q = (i & 15) * 4;
                float4 v = *(const float4*)&ea[(size_t)(e0 + r) * 128 + kc + q];
                split4(v, Ah + r * LD + q, Al + r * LD + q);
            }
            stage_B(Bh, Bl, WOF_W1B, 128, nc * 128, kc, tid);
            __syncthreads();
            warp_gemm64(Ah, Al, Bh, Bl, acc, wm, wn);
        }
        __syncthreads();
        store_C(Cs, acc, wm, wn);
        __syncthreads();
        {
            const float* Pr = g_P + (size_t)rs[er] * HID + nc * 128 + ec0;
            float* Ar = g_agg + (size_t)cs[er] * HID + nc * 128 + ec0;
#pragma unroll
            for (int q = 0; q < 64; q++)
                atomicAdd(Ar + q, fmaxf(Cs[er * 128 + ec0 + q] + Pr[q], 0.f));
        }
    }
    if (tid < 128) atomicAdd(&g_cnt[cs[tid]], 1.0f);
}

// ------------------------- agg2: (agg*rc) @ W2 + b2*ind (K=256, N=256) -----------------
__global__ __launch_bounds__(256, 2) void agg2_kernel(const float* __restrict__ b2) {
    GEMM_VARS();
    __shared__ float rcs[128], inds[128];
    int m0 = blockIdx.x * 128;
    if (tid < 128) {
        int n = m0 + tid;
        float c = (n < NN) ? g_cnt[n] : 0.f;
        rcs[tid] = 1.0f / fmaxf(c, 1.0f);
        inds[tid] = (c > 0.f) ? 1.0f : 0.f;
    }
    for (int nc = 0; nc < 2; nc++) {
        FragC acc[2][4];
#pragma unroll
        for (int mi = 0; mi < 2; mi++)
#pragma unroll
            for (int ni = 0; ni < 4; ni++) wmma::fill_fragment(acc[mi][ni], 0.f);
        for (int kc = 0; kc < 256; kc += 64) {
            __syncthreads();
            for (int i = tid; i < 2048; i += 256) {
                int r = i >> 4, q = (i & 15) * 4;
                int n = m0 + r;
                float4 v = make_float4(0.f, 0.f, 0.f, 0.f);
                if (n < NN) {
                    v = *(const float4*)&g_agg[(size_t)n * HID + kc + q];
                    float rc = rcs[r];
                    v.x *= rc; v.y *= rc; v.z *= rc; v.w *= rc;
                }
                split4(v, Ah + r * LD + q, Al + r * LD + q);
            }
            stage_B(Bh, Bl, WOF_W2, 256, nc * 128, kc, tid);
            __syncthreads();
            warp_gemm64(Ah, Al, Bh, Bl, acc, wm, wn);
        }
        __syncthreads();
        store_C(Cs, acc, wm, wn);
        __syncthreads();
        int n = m0 + er;
        if (n < NN) {
            float ind = inds[er];
            float* dst = &g_hagg[(size_t)n * HID + nc * 128 + ec0];
            const float* bb = b2 + nc * 128 + ec0;
#pragma unroll
            for (int q = 0; q < 64; q++)
                dst[q] = Cs[er * 128 + ec0 + q] + __ldg(bb + q) * ind;
        }
    }
}

// ------------------------- node1: t = relu([x||hagg||u]@W3+b3) -> g_P (K=448, N=256) ---
__global__ __launch_bounds__(256, 2) void node1_kernel(const float* __restrict__ x,
                                                       const float* __restrict__ u,
                                                       const void* __restrict__ batch,
                                                       const float* __restrict__ b3) {
    GEMM_VARS();
    __shared__ int bts[128];
    int m0 = blockIdx.x * 128;
    if (tid < 128) {
        int n = m0 + tid;
        int b = (n < NN) ? load_index(batch, n) : 0;
        bts[tid] = (b < 64) ? b : 0;
    }
    for (int nc = 0; nc < 2; nc++) {
        FragC acc[2][4];
#pragma unroll
        for (int mi = 0; mi < 2; mi++)
#pragma unroll
            for (int ni = 0; ni < 4; ni++) wmma::fill_fragment(acc[mi][ni], 0.f);
        for (int kc = 0; kc < 448; kc += 64) {
            __syncthreads();
            for (int i = tid; i < 2048; i += 256) {
                int r = i >> 4, q = (i & 15) * 4;
                int n = m0 + r;
                int k = kc + q;
                float4 v = make_float4(0.f, 0.f, 0.f, 0.f);
                if (n < NN) {
                    if (k < 128)      v = *(const float4*)&x[(size_t)n * 128 + k];
                    else if (k < 384) v = *(const float4*)&g_hagg[(size_t)n * HID + (k - 128)];
                    else              v = *(const float4*)&u[bts[r] * 64 + (k - 384)];
                }
                split4(v, Ah + r * LD + q, Al + r * LD + q);
            }
            stage_B(Bh, Bl, WOF_W3, 448, nc * 128, kc, tid);
            __syncthreads();
            warp_gemm64(Ah, Al, Bh, Bl, acc, wm, wn);
        }
        __syncthreads();
        store_C(Cs, acc, wm, wn);
        __syncthreads();
        int n = m0 + er;
        if (n < NN) {
            float* dst = &g_P[(size_t)n * HID + nc * 128 + ec0];
            const float* bb = b3 + nc * 128 + ec0;
#pragma unroll
            for (int q = 0; q < 64; q++)
                dst[q] = fmaxf(Cs[er * 128 + ec0 + q] + __ldg(bb + q), 0.f);
        }
    }
}

// ------------------------- node2: out = t @ W4 + b4 (K=256, N=128) ---------------------
__global__ __launch_bounds__(256, 2) void node2_kernel(const float* __restrict__ b4,
                                                       float* __restrict__ out) {
    GEMM_VARS();
    int m0 = blockIdx.x * 128;
    FragC acc[2][4];
#pragma unroll
    for (int mi = 0; mi < 2; mi++)
#pragma unroll
        for (int ni = 0; ni < 4; ni++) wmma::fill_fragment(acc[mi][ni], 0.f);
    for (int kc = 0; kc < 256; kc += 64) {
        __syncthreads();
        for (int i = tid; i < 2048; i += 256) {
            int r = i >> 4, q = (i & 15) * 4;
            int n = m0 + r;
            float4 v = (n < NN) ? *(const float4*)&g_P[(size_t)n * HID + kc + q]
                                : make_float4(0.f, 0.f, 0.f, 0.f);
            split4(v, Ah + r * LD + q, Al + r * LD + q);
        }
        stage_B(Bh, Bl, WOF_W4, 256, 0, kc, tid);
        __syncthreads();
        warp_gemm64(Ah, Al, Bh, Bl, acc, wm, wn);
    }
    __syncthreads();
    store_C(Cs, acc, wm, wn);
    __syncthreads();
    int n = m0 + er;
    if (n < NN) {
        float* dst = &out[(size_t)n * 128 + ec0];
        const float* bb = b4 + ec0;
#pragma unroll
        for (int q = 0; q < 64; q++) dst[q] = Cs[er * 128 + ec0 + q] + __ldg(bb + q);
    }
}

// ---------------------------------------------------------------------------
extern "C" void kernel_launch(void* const* d_in, const int* in_sizes, int n_in,
                              void* d_out, int out_size) {
    const float* x     = (const float*)d_in[0];
    const void*  ei    = d_in[1];
    const float* ea    = (const float*)d_in[2];
    const float* u     = (const float*)d_in[3];
    const void*  batch = d_in[4];
    const float* W1    = (const float*)d_in[5];
    const float* b1    = (const float*)d_in[6];
    const float* W2    = (const float*)d_in[7];
    const float* b2    = (const float*)d_in[8];
    const float* W3    = (const float*)d_in[9];
    const float* b3    = (const float*)d_in[10];
    const float* W4    = (const float*)d_in[11];
    const float* b4    = (const float*)d_in[12];
    float* out = (float*)d_out;

    static int attr_done = 0;
    if (!attr_done) {
        cudaFuncSetAttribute(p_kernel,     cudaFuncAttributeMaxDynamicSharedMemorySize, SMEM_TOTAL);
        cudaFuncSetAttribute(edge_kernel,  cudaFuncAttributeMaxDynamicSharedMemorySize, SMEM_TOTAL);
        cudaFuncSetAttribute(agg2_kernel,  cudaFuncAttributeMaxDynamicSharedMemorySize, SMEM_TOTAL);
        cudaFuncSetAttribute(node1_kernel, cudaFuncAttributeMaxDynamicSharedMemorySize, SMEM_TOTAL);
        cudaFuncSetAttribute(node2_kernel, cudaFuncAttributeMaxDynamicSharedMemorySize, SMEM_TOTAL);
        attr_done = 1;
    }

    int nblk = (NN + 127) / 128;
    zero_kernel<<<2048, 256>>>(ei);
    prep_kernel<<<512, 256>>>(W1, W2, W3, W4);
    p_kernel<<<nblk, 256, SMEM_TOTAL>>>(x, b1);
    edge_kernel<<<NE / 128, 256, SMEM_TOTAL>>>(ea, ei);
    agg2_kernel<<<nblk, 256, SMEM_TOTAL>>>(b2);
    node1_kernel<<<nblk, 256, SMEM_TOTAL>>>(x, u, batch, b3);
    node2_kernel<<<nblk, 256, SMEM_TOTAL>>>(b4, out);
}

// round 10
// speedup vs baseline: 6.9614x; 1.7832x over previous
#include <cuda_runtime.h>
#include <cuda_bf16.h>
#include <mma.h>
#include <cstdint>

using namespace nvcuda;

#define NN   50000
#define NE   640000
#define HID  256
#define LD   80

#define WOF_W1A 0
#define WOF_W1B 32768
#define WOF_W2  65536
#define WOF_W3  131072
#define WOF_W4  245760
#define WB_HALF 278528

__device__ __align__(16) __nv_bfloat16 g_wb[2 * WB_HALF];
__device__ float g_P[NN * HID];      // P = x@W1a+b1; later reused as t-scratch
__device__ float g_agg[NN * HID];
__device__ float g_hagg[NN * HID];
__device__ float g_cnt[NN];
__device__ int   g_is64;

#define SMEM_TOTAL 131072
// dynamic smem (bf16 elems): Ah[0..10240) Al[10240..20480) Bh[20480..40960) Bl[40960..61440)

// ---------------------------------------------------------------------------
__global__ void zero_kernel(const void* ei_raw) {
    int idx = blockIdx.x * blockDim.x + threadIdx.x;
    int stride = gridDim.x * blockDim.x;
    for (int i = idx; i < NN * HID; i += stride) g_agg[i] = 0.f;
    for (int i = idx; i < NN; i += stride) g_cnt[i] = 0.f;
    if (idx == 0) {
        const long long* p = (const long long*)ei_raw;
        int ok = 1;
        for (int i = 0; i < 1024; i++) {
            long long v = p[i];
            if (v < 0 || v >= NN) { ok = 0; break; }
        }
        g_is64 = ok;
    }
}

__device__ __forceinline__ int load_index(const void* p, long long i) {
    long long v = g_is64 ? ((const long long*)p)[i] : (long long)((const int*)p)[i];
    if (v < 0) v = 0;
    if (v >= NN) v = NN - 1;
    return (int)v;
}

__global__ void prep_kernel(const float* __restrict__ W1, const float* __restrict__ W2,
                            const float* __restrict__ W3, const float* __restrict__ W4) {
    int i = blockIdx.x * blockDim.x + threadIdx.x;
    int stride = gridDim.x * blockDim.x;
    for (; i < WB_HALF; i += stride) {
        float v; int l, n, k;
        if (i < 32768)       { l = i;          n = l >> 7; k = l & 127; v = W1[k * 256 + n]; }
        else if (i < 65536)  { l = i - 32768;  n = l >> 7; k = l & 127; v = W1[(k + 128) * 256 + n]; }
        else if (i < 131072) { l = i - 65536;  n = l >> 8; k = l & 255; v = W2[k * 256 + n]; }
        else if (i < 245760) { l = i - 131072; n = l / 448; k = l % 448; v = W3[k * 256 + n]; }
        else                 { l = i - 245760; n = l >> 8; k = l & 255; v = W4[k * 128 + n]; }
        __nv_bfloat16 h = __float2bfloat16(v);
        g_wb[i] = h;
        g_wb[WB_HALF + i] = __float2bfloat16(v - __bfloat162float(h));
    }
}

// ---------------------------------------------------------------------------
typedef wmma::fragment<wmma::accumulator, 16, 16, 16, float> FragC;

__device__ __forceinline__ void split4(float4 v, __nv_bfloat16* h, __nv_bfloat16* l) {
    float a[4] = {v.x, v.y, v.z, v.w};
#pragma unroll
    for (int i = 0; i < 4; i++) {
        __nv_bfloat16 hi = __float2bfloat16(a[i]);
        h[i] = hi;
        l[i] = __float2bfloat16(a[i] - __bfloat162float(hi));
    }
}

__device__ __forceinline__ void red_add4(float* p, float4 v) {
    asm volatile("red.global.add.v4.f32 [%0], {%1,%2,%3,%4};"
                 :: "l"(p), "f"(v.x), "f"(v.y), "f"(v.z), "f"(v.w) : "memory");
}
__device__ __forceinline__ void red_add1(float* p, float v) {
    asm volatile("red.global.add.f32 [%0], %1;" :: "l"(p), "f"(v) : "memory");
}

// stage NB rows x 64 cols of B (hi+lo) from g_wb [NxK] into smem
__device__ __forceinline__ void stage_B(__nv_bfloat16* Bh, __nv_bfloat16* Bl,
                                        int wof, int K, int kc, int tid, int NB) {
    const __nv_bfloat16* sh = g_wb + wof + kc;
    const __nv_bfloat16* sl = sh + WB_HALF;
    for (int i = tid; i < NB * 8; i += 256) {
        int n = i >> 3, kq = (i & 7) * 8;
        *(uint4*)(Bh + n * LD + kq) = *(const uint4*)(sh + (size_t)n * K + kq);
        *(uint4*)(Bl + n * LD + kq) = *(const uint4*)(sl + (size_t)n * K + kq);
    }
}

// one 64-deep K chunk: warp tile 64 x (16*NI), 3-term bf16 split
template<int NI>
__device__ __forceinline__ void warp_gemm64(const __nv_bfloat16* Ah, const __nv_bfloat16* Al,
                                            const __nv_bfloat16* Bh, const __nv_bfloat16* Bl,
                                            FragC acc[4][NI], int wm, int wn) {
#pragma unroll
    for (int kk = 0; kk < 64; kk += 16) {
        wmma::fragment<wmma::matrix_a, 16, 16, 16, __nv_bfloat16, wmma::row_major> ah[4], al[4];
#pragma unroll
        for (int mi = 0; mi < 4; mi++) {
            wmma::load_matrix_sync(ah[mi], Ah + (wm * 64 + mi * 16) * LD + kk, LD);
            wmma::load_matrix_sync(al[mi], Al + (wm * 64 + mi * 16) * LD + kk, LD);
        }
#pragma unroll
        for (int ni = 0; ni < NI; ni++) {
            wmma::fragment<wmma::matrix_b, 16, 16, 16, __nv_bfloat16, wmma::col_major> bh, bl;
            wmma::load_matrix_sync(bh, Bh + (wn * 16 * NI + ni * 16) * LD + kk, LD);
            wmma::load_matrix_sync(bl, Bl + (wn * 16 * NI + ni * 16) * LD + kk, LD);
#pragma unroll
            for (int mi = 0; mi < 4; mi++) {
                wmma::mma_sync(acc[mi][ni], ah[mi], bh, acc[mi][ni]);
                wmma::mma_sync(acc[mi][ni], al[mi], bh, acc[mi][ni]);
                wmma::mma_sync(acc[mi][ni], ah[mi], bl, acc[mi][ni]);
            }
        }
    }
}

template<int NI>
__device__ __forceinline__ void store_warpC(float* Cw, FragC acc[4][NI]) {
#pragma unroll
    for (int mi = 0; mi < 4; mi++)
#pragma unroll
        for (int ni = 0; ni < NI; ni++)
            wmma::store_matrix_sync(Cw + (mi * 16) * (NI * 16) + ni * 16,
                                    acc[mi][ni], NI * 16, wmma::mem_row_major);
}

#define GEMM_VARS() \
    extern __shared__ char smem[]; \
    __nv_bfloat16* Ah = (__nv_bfloat16*)smem; \
    __nv_bfloat16* Al = Ah + 10240; \
    __nv_bfloat16* Bh = Al + 10240; \
    __nv_bfloat16* Bl = Bh + 20480; \
    int tid = threadIdx.x, lane = tid & 31, w = tid >> 5, wm = w & 1, wn = w >> 1;

// ------------------------- p: P = x @ W1a + b1 (K=128, N=256) --------------
__global__ __launch_bounds__(256, 1) void p_kernel(const float* __restrict__ x,
                                                   const float* __restrict__ b1) {
    GEMM_VARS();
    int m0 = blockIdx.x * 128;
    FragC acc[4][4];
#pragma unroll
    for (int mi = 0; mi < 4; mi++)
#pragma unroll
        for (int ni = 0; ni < 4; ni++) wmma::fill_fragment(acc[mi][ni], 0.f);
    for (int kc = 0; kc < 128; kc += 64) {
        __syncthreads();
        for (int i = tid; i < 2048; i += 256) {
            int r = i >> 4, q = (i & 15) * 4;
            int n = m0 + r;
            float4 v = (n < NN) ? *(const float4*)&x[(size_t)n * 128 + kc + q]
                                : make_float4(0.f, 0.f, 0.f, 0.f);
            split4(v, Ah + r * LD + q, Al + r * LD + q);
        }
        stage_B(Bh, Bl, WOF_W1A, 128, kc, tid, 256);
        __syncthreads();
        warp_gemm64<4>(Ah, Al, Bh, Bl, acc, wm, wn);
    }
    __syncthreads();
    float* Cw = (float*)smem + w * 4096;
    store_warpC<4>(Cw, acc);
    __syncwarp();
    for (int i2 = lane; i2 < 1024; i2 += 32) {
        int r = i2 >> 4, c = (i2 & 15) * 4;
        int n = m0 + wm * 64 + r;
        if (n < NN) {
            int col = wn * 64 + c;
            float4 cv = *(float4*)(Cw + r * 64 + c);
            cv.x += __ldg(&b1[col]);     cv.y += __ldg(&b1[col + 1]);
            cv.z += __ldg(&b1[col + 2]); cv.w += __ldg(&b1[col + 3]);
            *(float4*)(g_P + (size_t)n * HID + col) = cv;
        }
    }
}

// ------------------------- edge: red-scatter relu(ea@W1b + P[row]) ---------
__global__ __launch_bounds__(256, 1) void edge_kernel(const float* __restrict__ ea,
                                                      const void* __restrict__ ei) {
    GEMM_VARS();
    __shared__ int rs[128], cs[128];
    int e0 = blockIdx.x * 128;
    if (tid < 128) {
        rs[tid] = load_index(ei, e0 + tid);
        cs[tid] = load_index(ei, (long long)NE + e0 + tid);
    }
    FragC acc[4][4];
#pragma unroll
    for (int mi = 0; mi < 4; mi++)
#pragma unroll
        for (int ni = 0; ni < 4; ni++) wmma::fill_fragment(acc[mi][ni], 0.f);
    for (int kc = 0; kc < 128; kc += 64) {
        __syncthreads();
        for (int i = tid; i < 2048; i += 256) {
            int r = i >> 4, q = (i & 15) * 4;
            float4 v = *(const float4*)&ea[(size_t)(e0 + r) * 128 + kc + q];
            split4(v, Ah + r * LD + q, Al + r * LD + q);
        }
        stage_B(Bh, Bl, WOF_W1B, 128, kc, tid, 256);
        __syncthreads();
        warp_gemm64<4>(Ah, Al, Bh, Bl, acc, wm, wn);
    }
    __syncthreads();
    float* Cw = (float*)smem + w * 4096;
    store_warpC<4>(Cw, acc);
    __syncwarp();
    for (int i2 = lane; i2 < 1024; i2 += 32) {
        int r = i2 >> 4, c = (i2 & 15) * 4;
        int lr = wm * 64 + r;
        int col = wn * 64 + c;
        float4 cv = *(float4*)(Cw + r * 64 + c);
        const float* Pr = g_P + (size_t)rs[lr] * HID + col;
        float4 pv = *(const float4*)Pr;
        float4 v;
        v.x = fmaxf(cv.x + pv.x, 0.f);
        v.y = fmaxf(cv.y + pv.y, 0.f);
        v.z = fmaxf(cv.z + pv.z, 0.f);
        v.w = fmaxf(cv.w + pv.w, 0.f);
        red_add4(g_agg + (size_t)cs[lr] * HID + col, v);
    }
    if (tid < 128) red_add1(&g_cnt[cs[tid]], 1.0f);
}

// ------------------------- agg2: (agg*rc) @ W2 + b2*ind (K=256, N=256) -----
__global__ __launch_bounds__(256, 1) void agg2_kernel(const float* __restrict__ b2) {
    GEMM_VARS();
    __shared__ float rcs[128], inds[128];
    int m0 = blockIdx.x * 128;
    if (tid < 128) {
        int n = m0 + tid;
        float c = (n < NN) ? g_cnt[n] : 0.f;
        rcs[tid] = 1.0f / fmaxf(c, 1.0f);
        inds[tid] = (c > 0.f) ? 1.0f : 0.f;
    }
    FragC acc[4][4];
#pragma unroll
    for (int mi = 0; mi < 4; mi++)
#pragma unroll
        for (int ni = 0; ni < 4; ni++) wmma::fill_fragment(acc[mi][ni], 0.f);
    for (int kc = 0; kc < 256; kc += 64) {
        __syncthreads();
        for (int i = tid; i < 2048; i += 256) {
            int r = i >> 4, q = (i & 15) * 4;
            int n = m0 + r;
            float4 v = make_float4(0.f, 0.f, 0.f, 0.f);
            if (n < NN) {
                v = *(const float4*)&g_agg[(size_t)n * HID + kc + q];
                float rc = rcs[r];
                v.x *= rc; v.y *= rc; v.z *= rc; v.w *= rc;
            }
            split4(v, Ah + r * LD + q, Al + r * LD + q);
        }
        stage_B(Bh, Bl, WOF_W2, 256, kc, tid, 256);
        __syncthreads();
        warp_gemm64<4>(Ah, Al, Bh, Bl, acc, wm, wn);
    }
    __syncthreads();
    float* Cw = (float*)smem + w * 4096;
    store_warpC<4>(Cw, acc);
    __syncwarp();
    for (int i2 = lane; i2 < 1024; i2 += 32) {
        int r = i2 >> 4, c = (i2 & 15) * 4;
        int n = m0 + wm * 64 + r;
        if (n < NN) {
            int col = wn * 64 + c;
            float ind = inds[wm * 64 + r];
            float4 cv = *(float4*)(Cw + r * 64 + c);
            cv.x += __ldg(&b2[col]) * ind;     cv.y += __ldg(&b2[col + 1]) * ind;
            cv.z += __ldg(&b2[col + 2]) * ind; cv.w += __ldg(&b2[col + 3]) * ind;
            *(float4*)(g_hagg + (size_t)n * HID + col) = cv;
        }
    }
}

// ------------------------- node1: t = relu([x||hagg||u]@W3+b3) -> g_P ------
__global__ __launch_bounds__(256, 1) void node1_kernel(const float* __restrict__ x,
                                                       const float* __restrict__ u,
                                                       const void* __restrict__ batch,
                                                       const float* __restrict__ b3) {
    GEMM_VARS();
    __shared__ int bts[128];
    int m0 = blockIdx.x * 128;
    if (tid < 128) {
        int n = m0 + tid;
        int b = (n < NN) ? load_index(batch, n) : 0;
        bts[tid] = (b < 64) ? b : 0;
    }
    FragC acc[4][4];
#pragma unroll
    for (int mi = 0; mi < 4; mi++)
#pragma unroll
        for (int ni = 0; ni < 4; ni++) wmma::fill_fragment(acc[mi][ni], 0.f);
    for (int kc = 0; kc < 448; kc += 64) {
        __syncthreads();
        for (int i = tid; i < 2048; i += 256) {
            int r = i >> 4, q = (i & 15) * 4;
            int n = m0 + r;
            int k = kc + q;
            float4 v = make_float4(0.f, 0.f, 0.f, 0.f);
            if (n < NN) {
                if (k < 128)      v = *(const float4*)&x[(size_t)n * 128 + k];
                else if (k < 384) v = *(const float4*)&g_hagg[(size_t)n * HID + (k - 128)];
                else              v = *(const float4*)&u[bts[r] * 64 + (k - 384)];
            }
            split4(v, Ah + r * LD + q, Al + r * LD + q);
        }
        stage_B(Bh, Bl, WOF_W3, 448, kc, tid, 256);
        __syncthreads();
        warp_gemm64<4>(Ah, Al, Bh, Bl, acc, wm, wn);
    }
    __syncthreads();
    float* Cw = (float*)smem + w * 4096;
    store_warpC<4>(Cw, acc);
    __syncwarp();
    for (int i2 = lane; i2 < 1024; i2 += 32) {
        int r = i2 >> 4, c = (i2 & 15) * 4;
        int n = m0 + wm * 64 + r;
        if (n < NN) {
            int col = wn * 64 + c;
            float4 cv = *(float4*)(Cw + r * 64 + c);
            cv.x = fmaxf(cv.x + __ldg(&b3[col]), 0.f);
            cv.y = fmaxf(cv.y + __ldg(&b3[col + 1]), 0.f);
            cv.z = fmaxf(cv.z + __ldg(&b3[col + 2]), 0.f);
            cv.w = fmaxf(cv.w + __ldg(&b3[col + 3]), 0.f);
            *(float4*)(g_P + (size_t)n * HID + col) = cv;
        }
    }
}

// ------------------------- node2: out = t @ W4 + b4 (K=256, N=128) ---------
__global__ __launch_bounds__(256, 1) void node2_kernel(const float* __restrict__ b4,
                                                       float* __restrict__ out) {
    GEMM_VARS();
    int m0 = blockIdx.x * 128;
    FragC acc[4][2];
#pragma unroll
    for (int mi = 0; mi < 4; mi++)
#pragma unroll
        for (int ni = 0; ni < 2; ni++) wmma::fill_fragment(acc[mi][ni], 0.f);
    for (int kc = 0; kc < 256; kc += 64) {
        __syncthreads();
        for (int i = tid; i < 2048; i += 256) {
            int r = i >> 4, q = (i & 15) * 4;
            int n = m0 + r;
            float4 v = (n < NN) ? *(const float4*)&g_P[(size_t)n * HID + kc + q]
                                : make_float4(0.f, 0.f, 0.f, 0.f);
            split4(v, Ah + r * LD + q, Al + r * LD + q);
        }
        stage_B(Bh, Bl, WOF_W4, 256, kc, tid, 128);
        __syncthreads();
        warp_gemm64<2>(Ah, Al, Bh, Bl, acc, wm, wn);
    }
    __syncthreads();
    float* Cw = (float*)smem + w * 2048;
    store_warpC<2>(Cw, acc);
    __syncwarp();
    for (int i2 = lane; i2 < 512; i2 += 32) {
        int r = i2 >> 3, c = (i2 & 7) * 4;
        int n = m0 + wm * 64 + r;
        if (n < NN) {
            int col = wn * 32 + c;
            float4 cv = *(float4*)(Cw + r * 32 + c);
            cv.x += __ldg(&b4[col]);     cv.y += __ldg(&b4[col + 1]);
            cv.z += __ldg(&b4[col + 2]); cv.w += __ldg(&b4[col + 3]);
            *(float4*)(out + (size_t)n * 128 + col) = cv;
        }
    }
}

// ---------------------------------------------------------------------------
extern "C" void kernel_launch(void* const* d_in, const int* in_sizes, int n_in,
                              void* d_out, int out_size) {
    const float* x     = (const float*)d_in[0];
    const void*  ei    = d_in[1];
    const float* ea    = (const float*)d_in[2];
    const float* u     = (const float*)d_in[3];
    const void*  batch = d_in[4];
    const float* W1    = (const float*)d_in[5];
    const float* b1    = (const float*)d_in[6];
    const float* W2    = (const float*)d_in[7];
    const float* b2    = (const float*)d_in[8];
    const float* W3    = (const float*)d_in[9];
    const float* b3    = (const float*)d_in[10];
    const float* W4    = (const float*)d_in[11];
    const float* b4    = (const float*)d_in[12];
    float* out = (float*)d_out;

    static int attr_done = 0;
    if (!attr_done) {
        cudaFuncSetAttribute(p_kernel,     cudaFuncAttributeMaxDynamicSharedMemorySize, SMEM_TOTAL);
        cudaFuncSetAttribute(edge_kernel,  cudaFuncAttributeMaxDynamicSharedMemorySize, SMEM_TOTAL);
        cudaFuncSetAttribute(agg2_kernel,  cudaFuncAttributeMaxDynamicSharedMemorySize, SMEM_TOTAL);
        cudaFuncSetAttribute(node1_kernel, cudaFuncAttributeMaxDynamicSharedMemorySize, SMEM_TOTAL);
        cudaFuncSetAttribute(node2_kernel, cudaFuncAttributeMaxDynamicSharedMemorySize, SMEM_TOTAL);
        attr_done = 1;
    }

    int nblk = (NN + 127) / 128;
    zero_kernel<<<2048, 256>>>(ei);
    prep_kernel<<<512, 256>>>(W1, W2, W3, W4);
    p_kernel<<<nblk, 256, SMEM_TOTAL>>>(x, b1);
    edge_kernel<<<NE / 128, 256, SMEM_TOTAL>>>(ea, ei);
    agg2_kernel<<<nblk, 256, SMEM_TOTAL>>>(b2);
    node1_kernel<<<nblk, 256, SMEM_TOTAL>>>(x, u, batch, b3);
    node2_kernel<<<nblk, 256, SMEM_TOTAL>>>(b4, out);
}

// round 11
// speedup vs baseline: 7.5735x; 1.0879x over previous
#include <cuda_runtime.h>
#include <cuda_bf16.h>
#include <mma.h>
#include <cstdint>

using namespace nvcuda;

#define NN   50000
#define NE   640000
#define HID  256
#define LD   80

#define WOF_W1A 0
#define WOF_W1B 32768
#define WOF_W2  65536
#define WOF_W3  131072
#define WOF_W4  245760
#define WB_HALF 278528

__device__ __align__(16) __nv_bfloat16 g_wb[2 * WB_HALF];
__device__ float g_P[NN * HID];      // P = x@W1a+b1; later reused as t-scratch
__device__ float g_agg[NN * HID];
__device__ float g_hagg[NN * HID];
__device__ float g_cnt[NN];
__device__ int   g_is64;

// dynamic smem: Ah[0,20480) Al Bh Bl bf16 elems (128 x LD each) = 81920 B
#define SMEM_TOTAL 81920

// ---------------------------------------------------------------------------
__global__ void zero_kernel(const void* ei_raw) {
    int idx = blockIdx.x * blockDim.x + threadIdx.x;
    int stride = gridDim.x * blockDim.x;
    for (int i = idx; i < NN * HID; i += stride) g_agg[i] = 0.f;
    for (int i = idx; i < NN; i += stride) g_cnt[i] = 0.f;
    if (idx == 0) {
        const long long* p = (const long long*)ei_raw;
        int ok = 1;
        for (int i = 0; i < 1024; i++) {
            long long v = p[i];
            if (v < 0 || v >= NN) { ok = 0; break; }
        }
        g_is64 = ok;
    }
}

__device__ __forceinline__ int load_index(const void* p, long long i) {
    long long v = g_is64 ? ((const long long*)p)[i] : (long long)((const int*)p)[i];
    if (v < 0) v = 0;
    if (v >= NN) v = NN - 1;
    return (int)v;
}

__global__ void prep_kernel(const float* __restrict__ W1, const float* __restrict__ W2,
                            const float* __restrict__ W3, const float* __restrict__ W4) {
    int i = blockIdx.x * blockDim.x + threadIdx.x;
    int stride = gridDim.x * blockDim.x;
    for (; i < WB_HALF; i += stride) {
        float v; int l, n, k;
        if (i < 32768)       { l = i;          n = l >> 7; k = l & 127; v = W1[k * 256 + n]; }
        else if (i < 65536)  { l = i - 32768;  n = l >> 7; k = l & 127; v = W1[(k + 128) * 256 + n]; }
        else if (i < 131072) { l = i - 65536;  n = l >> 8; k = l & 255; v = W2[k * 256 + n]; }
        else if (i < 245760) { l = i - 131072; n = l / 448; k = l % 448; v = W3[k * 256 + n]; }
        else                 { l = i - 245760; n = l >> 8; k = l & 255; v = W4[k * 128 + n]; }
        __nv_bfloat16 h = __float2bfloat16(v);
        g_wb[i] = h;
        g_wb[WB_HALF + i] = __float2bfloat16(v - __bfloat162float(h));
    }
}

// ---------------------------------------------------------------------------
typedef wmma::fragment<wmma::accumulator, 16, 16, 16, float> FragC;

__device__ __forceinline__ void split4(float4 v, __nv_bfloat16* h, __nv_bfloat16* l) {
    float a[4] = {v.x, v.y, v.z, v.w};
#pragma unroll
    for (int i = 0; i < 4; i++) {
        __nv_bfloat16 hi = __float2bfloat16(a[i]);
        h[i] = hi;
        l[i] = __float2bfloat16(a[i] - __bfloat162float(hi));
    }
}

__device__ __forceinline__ void red_add4(float* p, float4 v) {
    asm volatile("red.global.add.v4.f32 [%0], {%1,%2,%3,%4};"
                 :: "l"(p), "f"(v.x), "f"(v.y), "f"(v.z), "f"(v.w) : "memory");
}
__device__ __forceinline__ void red_add1(float* p, float v) {
    asm volatile("red.global.add.f32 [%0], %1;" :: "l"(p), "f"(v) : "memory");
}

// async-stage 128 N-rows x 64 K of B (hi+lo) from g_wb [NxK]
__device__ __forceinline__ void stage_B_async(__nv_bfloat16* Bh, __nv_bfloat16* Bl,
                                              int wof, int K, int n0, int kc, int tid) {
    const __nv_bfloat16* sh = g_wb + wof + (size_t)n0 * K + kc;
    const __nv_bfloat16* sl = sh + WB_HALF;
    for (int i = tid; i < 1024; i += 128) {
        int n = i >> 3, kq = (i & 7) * 8;
        uint32_t dh = (uint32_t)__cvta_generic_to_shared(Bh + n * LD + kq);
        uint32_t dl = (uint32_t)__cvta_generic_to_shared(Bl + n * LD + kq);
        asm volatile("cp.async.cg.shared.global [%0], [%1], 16;" :: "r"(dh), "l"(sh + (size_t)n * K + kq));
        asm volatile("cp.async.cg.shared.global [%0], [%1], 16;" :: "r"(dl), "l"(sl + (size_t)n * K + kq));
    }
    asm volatile("cp.async.commit_group;" ::: "memory");
}
#define CP_WAIT() asm volatile("cp.async.wait_group 0;" ::: "memory")

// one 64-deep K chunk: warp tile 64x64, 3-term bf16 split
__device__ __forceinline__ void warp_gemm64(const __nv_bfloat16* Ah, const __nv_bfloat16* Al,
                                            const __nv_bfloat16* Bh, const __nv_bfloat16* Bl,
                                            FragC acc[4][4], int wm, int wn) {
#pragma unroll
    for (int kk = 0; kk < 64; kk += 16) {
        wmma::fragment<wmma::matrix_a, 16, 16, 16, __nv_bfloat16, wmma::row_major> ah[4], al[4];
#pragma unroll
        for (int mi = 0; mi < 4; mi++) {
            wmma::load_matrix_sync(ah[mi], Ah + (wm * 64 + mi * 16) * LD + kk, LD);
            wmma::load_matrix_sync(al[mi], Al + (wm * 64 + mi * 16) * LD + kk, LD);
        }
#pragma unroll
        for (int ni = 0; ni < 4; ni++) {
            wmma::fragment<wmma::matrix_b, 16, 16, 16, __nv_bfloat16, wmma::col_major> bh, bl;
            wmma::load_matrix_sync(bh, Bh + (wn * 64 + ni * 16) * LD + kk, LD);
            wmma::load_matrix_sync(bl, Bl + (wn * 64 + ni * 16) * LD + kk, LD);
#pragma unroll
            for (int mi = 0; mi < 4; mi++) {
                wmma::mma_sync(acc[mi][ni], ah[mi], bh, acc[mi][ni]);
                wmma::mma_sync(acc[mi][ni], al[mi], bh, acc[mi][ni]);
                wmma::mma_sync(acc[mi][ni], ah[mi], bl, acc[mi][ni]);
            }
        }
    }
}

__device__ __forceinline__ void store_warpC(float* Cw, FragC acc[4][4]) {
#pragma unroll
    for (int mi = 0; mi < 4; mi++)
#pragma unroll
        for (int ni = 0; ni < 4; ni++)
            wmma::store_matrix_sync(Cw + (mi * 16) * 64 + ni * 16, acc[mi][ni], 64,
                                    wmma::mem_row_major);
}

// 128 threads: 4 warps in 2x2 grid of 64x64 tiles; CTA tile 128(M) x 128(N);
// blockIdx.y selects the N-half (for N=256 layers).
#define GEMM_VARS() \
    extern __shared__ char smem[]; \
    __nv_bfloat16* Ah = (__nv_bfloat16*)smem; \
    __nv_bfloat16* Al = Ah + 128 * LD; \
    __nv_bfloat16* Bh = Al + 128 * LD; \
    __nv_bfloat16* Bl = Bh + 128 * LD; \
    int tid = threadIdx.x, lane = tid & 31, w = tid >> 5, wm = w & 1, wn = w >> 1; \
    int ny = blockIdx.y; \
    FragC acc[4][4]; \
    _Pragma("unroll") for (int mi = 0; mi < 4; mi++) \
    _Pragma("unroll") for (int ni = 0; ni < 4; ni++) wmma::fill_fragment(acc[mi][ni], 0.f);

#define EPILOGUE_SETUP() \
    __syncthreads(); \
    float* Cw = (float*)smem + w * 4096; \
    store_warpC(Cw, acc); \
    __syncwarp();

// ------------------------- p: P = x @ W1a + b1 (K=128, N=256) --------------
__global__ __launch_bounds__(128, 2) void p_kernel(const float* __restrict__ x,
                                                   const float* __restrict__ b1) {
    GEMM_VARS();
    int m0 = blockIdx.x * 128;
    for (int kc = 0; kc < 128; kc += 64) {
        __syncthreads();
        stage_B_async(Bh, Bl, WOF_W1A, 128, ny * 128, kc, tid);
        for (int i = tid; i < 2048; i += 128) {
            int r = i >> 4, q = (i & 15) * 4;
            int n = m0 + r;
            float4 v = (n < NN) ? *(const float4*)&x[(size_t)n * 128 + kc + q]
                                : make_float4(0.f, 0.f, 0.f, 0.f);
            split4(v, Ah + r * LD + q, Al + r * LD + q);
        }
        CP_WAIT();
        __syncthreads();
        warp_gemm64(Ah, Al, Bh, Bl, acc, wm, wn);
    }
    EPILOGUE_SETUP();
    for (int i2 = lane; i2 < 1024; i2 += 32) {
        int r = i2 >> 4, c = (i2 & 15) * 4;
        int n = m0 + wm * 64 + r;
        if (n < NN) {
            int col = ny * 128 + wn * 64 + c;
            float4 cv = *(float4*)(Cw + r * 64 + c);
            cv.x += __ldg(&b1[col]);     cv.y += __ldg(&b1[col + 1]);
            cv.z += __ldg(&b1[col + 2]); cv.w += __ldg(&b1[col + 3]);
            *(float4*)(g_P + (size_t)n * HID + col) = cv;
        }
    }
}

// ------------------------- edge: red-scatter relu(ea@W1b + P[row]) ---------
__global__ __launch_bounds__(128, 2) void edge_kernel(const float* __restrict__ ea,
                                                      const void* __restrict__ ei) {
    GEMM_VARS();
    __shared__ int rs[128], cs[128];
    int e0 = blockIdx.x * 128;
    rs[tid] = load_index(ei, e0 + tid);
    cs[tid] = load_index(ei, (long long)NE + e0 + tid);
    for (int kc = 0; kc < 128; kc += 64) {
        __syncthreads();
        stage_B_async(Bh, Bl, WOF_W1B, 128, ny * 128, kc, tid);
        for (int i = tid; i < 2048; i += 128) {
            int r = i >> 4, q = (i & 15) * 4;
            float4 v = *(const float4*)&ea[(size_t)(e0 + r) * 128 + kc + q];
            split4(v, Ah + r * LD + q, Al + r * LD + q);
        }
        CP_WAIT();
        __syncthreads();
        warp_gemm64(Ah, Al, Bh, Bl, acc, wm, wn);
    }
    EPILOGUE_SETUP();
    for (int i2 = lane; i2 < 1024; i2 += 32) {
        int r = i2 >> 4, c = (i2 & 15) * 4;
        int lr = wm * 64 + r;
        int col = ny * 128 + wn * 64 + c;
        float4 cv = *(float4*)(Cw + r * 64 + c);
        float4 pv = *(const float4*)(g_P + (size_t)rs[lr] * HID + col);
        float4 v;
        v.x = fmaxf(cv.x + pv.x, 0.f);
        v.y = fmaxf(cv.y + pv.y, 0.f);
        v.z = fmaxf(cv.z + pv.z, 0.f);
        v.w = fmaxf(cv.w + pv.w, 0.f);
        red_add4(g_agg + (size_t)cs[lr] * HID + col, v);
    }
    if (ny == 0) red_add1(&g_cnt[cs[tid]], 1.0f);
}

// ------------------------- agg2: (agg*rc) @ W2 + b2*ind (K=256, N=256) -----
__global__ __launch_bounds__(128, 2) void agg2_kernel(const float* __restrict__ b2) {
    GEMM_VARS();
    __shared__ float rcs[128], inds[128];
    int m0 = blockIdx.x * 128;
    {
        int n = m0 + tid;
        float c = (n < NN) ? g_cnt[n] : 0.f;
        rcs[tid] = 1.0f / fmaxf(c, 1.0f);
        inds[tid] = (c > 0.f) ? 1.0f : 0.f;
    }
    for (int kc = 0; kc < 256; kc += 64) {
        __syncthreads();
        stage_B_async(Bh, Bl, WOF_W2, 256, ny * 128, kc, tid);
        for (int i = tid; i < 2048; i += 128) {
            int r = i >> 4, q = (i & 15) * 4;
            int n = m0 + r;
            float4 v = make_float4(0.f, 0.f, 0.f, 0.f);
            if (n < NN) {
                v = *(const float4*)&g_agg[(size_t)n * HID + kc + q];
                float rc = rcs[r];
                v.x *= rc; v.y *= rc; v.z *= rc; v.w *= rc;
            }
            split4(v, Ah + r * LD + q, Al + r * LD + q);
        }
        CP_WAIT();
        __syncthreads();
        warp_gemm64(Ah, Al, Bh, Bl, acc, wm, wn);
    }
    EPILOGUE_SETUP();
    for (int i2 = lane; i2 < 1024; i2 += 32) {
        int r = i2 >> 4, c = (i2 & 15) * 4;
        int n = m0 + wm * 64 + r;
        if (n < NN) {
            int col = ny * 128 + wn * 64 + c;
            float ind = inds[wm * 64 + r];
            float4 cv = *(float4*)(Cw + r * 64 + c);
            cv.x += __ldg(&b2[col]) * ind;     cv.y += __ldg(&b2[col + 1]) * ind;
            cv.z += __ldg(&b2[col + 2]) * ind; cv.w += __ldg(&b2[col + 3]) * ind;
            *(float4*)(g_hagg + (size_t)n * HID + col) = cv;
        }
    }
}

// ------------------------- node1: t = relu([x||hagg||u]@W3+b3) -> g_P ------
__global__ __launch_bounds__(128, 2) void node1_kernel(const float* __restrict__ x,
                                                       const float* __restrict__ u,
                                                       const void* __restrict__ batch,
                                                       const float* __restrict__ b3) {
    GEMM_VARS();
    __shared__ int bts[128];
    int m0 = blockIdx.x * 128;
    {
        int n = m0 + tid;
        int b = (n < NN) ? load_index(batch, n) : 0;
        bts[tid] = (b < 64) ? b : 0;
    }
    for (int kc = 0; kc < 448; kc += 64) {
        __syncthreads();
        stage_B_async(Bh, Bl, WOF_W3, 448, ny * 128, kc, tid);
        for (int i = tid; i < 2048; i += 128) {
            int r = i >> 4, q = (i & 15) * 4;
            int n = m0 + r;
            int k = kc + q;
            float4 v = make_float4(0.f, 0.f, 0.f, 0.f);
            if (n < NN) {
                if (k < 128)      v = *(const float4*)&x[(size_t)n * 128 + k];
                else if (k < 384) v = *(const float4*)&g_hagg[(size_t)n * HID + (k - 128)];
                else              v = *(const float4*)&u[bts[r] * 64 + (k - 384)];
            }
            split4(v, Ah + r * LD + q, Al + r * LD + q);
        }
        CP_WAIT();
        __syncthreads();
        warp_gemm64(Ah, Al, Bh, Bl, acc, wm, wn);
    }
    EPILOGUE_SETUP();
    for (int i2 = lane; i2 < 1024; i2 += 32) {
        int r = i2 >> 4, c = (i2 & 15) * 4;
        int n = m0 + wm * 64 + r;
        if (n < NN) {
            int col = ny * 128 + wn * 64 + c;
            float4 cv = *(float4*)(Cw + r * 64 + c);
            cv.x = fmaxf(cv.x + __ldg(&b3[col]), 0.f);
            cv.y = fmaxf(cv.y + __ldg(&b3[col + 1]), 0.f);
            cv.z = fmaxf(cv.z + __ldg(&b3[col + 2]), 0.f);
            cv.w = fmaxf(cv.w + __ldg(&b3[col + 3]), 0.f);
            *(float4*)(g_P + (size_t)n * HID + col) = cv;
        }
    }
}

// ------------------------- node2: out = t @ W4 + b4 (K=256, N=128) ---------
__global__ __launch_bounds__(128, 2) void node2_kernel(const float* __restrict__ b4,
                                                       float* __restrict__ out) {
    GEMM_VARS();
    (void)ny;
    int m0 = blockIdx.x * 128;
    for (int kc = 0; kc < 256; kc += 64) {
        __syncthreads();
        stage_B_async(Bh, Bl, WOF_W4, 256, 0, kc, tid);
        for (int i = tid; i < 2048; i += 128) {
            int r = i >> 4, q = (i & 15) * 4;
            int n = m0 + r;
            float4 v = (n < NN) ? *(const float4*)&g_P[(size_t)n * HID + kc + q]
                                : make_float4(0.f, 0.f, 0.f, 0.f);
            split4(v, Ah + r * LD + q, Al + r * LD + q);
        }
        CP_WAIT();
        __syncthreads();
        warp_gemm64(Ah, Al, Bh, Bl, acc, wm, wn);
    }
    EPILOGUE_SETUP();
    for (int i2 = lane; i2 < 1024; i2 += 32) {
        int r = i2 >> 4, c = (i2 & 15) * 4;
        int n = m0 + wm * 64 + r;
        if (n < NN) {
            int col = wn * 64 + c;
            float4 cv = *(float4*)(Cw + r * 64 + c);
            cv.x += __ldg(&b4[col]);     cv.y += __ldg(&b4[col + 1]);
            cv.z += __ldg(&b4[col + 2]); cv.w += __ldg(&b4[col + 3]);
            *(float4*)(out + (size_t)n * 128 + col) = cv;
        }
    }
}

// ---------------------------------------------------------------------------
extern "C" void kernel_launch(void* const* d_in, const int* in_sizes, int n_in,
                              void* d_out, int out_size) {
    const float* x     = (const float*)d_in[0];
    const void*  ei    = d_in[1];
    const float* ea    = (const float*)d_in[2];
    const float* u     = (const float*)d_in[3];
    const void*  batch = d_in[4];
    const float* W1    = (const float*)d_in[5];
    const float* b1    = (const float*)d_in[6];
    const float* W2    = (const float*)d_in[7];
    const float* b2    = (const float*)d_in[8];
    const float* W3    = (const float*)d_in[9];
    const float* b3    = (const float*)d_in[10];
    const float* W4    = (const float*)d_in[11];
    const float* b4    = (const float*)d_in[12];
    float* out = (float*)d_out;

    static int attr_done = 0;
    if (!attr_done) {
        cudaFuncSetAttribute(p_kernel,     cudaFuncAttributeMaxDynamicSharedMemorySize, SMEM_TOTAL);
        cudaFuncSetAttribute(edge_kernel,  cudaFuncAttributeMaxDynamicSharedMemorySize, SMEM_TOTAL);
        cudaFuncSetAttribute(agg2_kernel,  cudaFuncAttributeMaxDynamicSharedMemorySize, SMEM_TOTAL);
        cudaFuncSetAttribute(node1_kernel, cudaFuncAttributeMaxDynamicSharedMemorySize, SMEM_TOTAL);
        cudaFuncSetAttribute(node2_kernel, cudaFuncAttributeMaxDynamicSharedMemorySize, SMEM_TOTAL);
        attr_done = 1;
    }

    int nblk = (NN + 127) / 128;
    dim3 g2(nblk, 2), ge(NE / 128, 2), g1(nblk, 1);
    zero_kernel<<<2048, 256>>>(ei);
    prep_kernel<<<512, 256>>>(W1, W2, W3, W4);
    p_kernel<<<g2, 128, SMEM_TOTAL>>>(x, b1);
    edge_kernel<<<ge, 128, SMEM_TOTAL>>>(ea, ei);
    agg2_kernel<<<g2, 128, SMEM_TOTAL>>>(b2);
    node1_kernel<<<g2, 128, SMEM_TOTAL>>>(x, u, batch, b3);
    node2_kernel<<<g1, 128, SMEM_TOTAL>>>(b4, out);
}

// round 12
// speedup vs baseline: 9.0269x; 1.1919x over previous
#include <cuda_runtime.h>
#include <cuda_bf16.h>
#include <mma.h>
#include <cstdint>

using namespace nvcuda;

#define NN   50000
#define NE   640000
#define HID  256
#define LD   72     // bf16 leading dim (144B stride -> conflict-free LDSM)
#define LDF  68     // fp32 staging leading dim

#define WOF_W1A 0
#define WOF_W1B 32768
#define WOF_W2  65536
#define WOF_W3  131072
#define WOF_W4  245760
#define WB_HALF 278528

__device__ __align__(16) __nv_bfloat16 g_wb[2 * WB_HALF];
__device__ float g_P[NN * HID];
__device__ float g_agg[NN * HID];
__device__ float g_hagg[NN * HID];
__device__ float g_cnt[NN];
__device__ int   g_is64;

// smem bytes: Ah 18432 | Al 18432 | Bh 18432 | Bl 18432 | Af32 34816 = 108544
#define OFF_AL  18432
#define OFF_BH  36864
#define OFF_BL  55296
#define OFF_AF  73728
#define SMEM_TOTAL 108544

// ---------------------------------------------------------------------------
__global__ void zero_kernel(const void* ei_raw) {
    int idx = blockIdx.x * blockDim.x + threadIdx.x;
    int stride = gridDim.x * blockDim.x;
    for (int i = idx; i < NN * HID; i += stride) g_agg[i] = 0.f;
    for (int i = idx; i < NN; i += stride) g_cnt[i] = 0.f;
    if (idx == 0) {
        const long long* p = (const long long*)ei_raw;
        int ok = 1;
        for (int i = 0; i < 1024; i++) {
            long long v = p[i];
            if (v < 0 || v >= NN) { ok = 0; break; }
        }
        g_is64 = ok;
    }
}

__device__ __forceinline__ int load_index(const void* p, long long i) {
    long long v = g_is64 ? ((const long long*)p)[i] : (long long)((const int*)p)[i];
    if (v < 0) v = 0;
    if (v >= NN) v = NN - 1;
    return (int)v;
}

__global__ void prep_kernel(const float* __restrict__ W1, const float* __restrict__ W2,
                            const float* __restrict__ W3, const float* __restrict__ W4) {
    int i = blockIdx.x * blockDim.x + threadIdx.x;
    int stride = gridDim.x * blockDim.x;
    for (; i < WB_HALF; i += stride) {
        float v; int l, n, k;
        if (i < 32768)       { l = i;          n = l >> 7; k = l & 127; v = W1[k * 256 + n]; }
        else if (i < 65536)  { l = i - 32768;  n = l >> 7; k = l & 127; v = W1[(k + 128) * 256 + n]; }
        else if (i < 131072) { l = i - 65536;  n = l >> 8; k = l & 255; v = W2[k * 256 + n]; }
        else if (i < 245760) { l = i - 131072; n = l / 448; k = l % 448; v = W3[k * 256 + n]; }
        else                 { l = i - 245760; n = l >> 8; k = l & 255; v = W4[k * 128 + n]; }
        __nv_bfloat16 h = __float2bfloat16(v);
        g_wb[i] = h;
        g_wb[WB_HALF + i] = __float2bfloat16(v - __bfloat162float(h));
    }
}

// ---------------------------------------------------------------------------
typedef wmma::fragment<wmma::accumulator, 16, 16, 16, float> FragC;

__device__ __forceinline__ void split4(float4 v, __nv_bfloat16* h, __nv_bfloat16* l) {
    float a[4] = {v.x, v.y, v.z, v.w};
#pragma unroll
    for (int i = 0; i < 4; i++) {
        __nv_bfloat16 hi = __float2bfloat16(a[i]);
        h[i] = hi;
        l[i] = __float2bfloat16(a[i] - __bfloat162float(hi));
    }
}
__device__ __forceinline__ void red_add4(float* p, float4 v) {
    asm volatile("red.global.add.v4.f32 [%0], {%1,%2,%3,%4};"
                 :: "l"(p), "f"(v.x), "f"(v.y), "f"(v.z), "f"(v.w) : "memory");
}
__device__ __forceinline__ void red_add1(float* p, float v) {
    asm volatile("red.global.add.f32 [%0], %1;" :: "l"(p), "f"(v) : "memory");
}
__device__ __forceinline__ void cpa16(void* d, const void* s) {
    uint32_t da = (uint32_t)__cvta_generic_to_shared(d);
    asm volatile("cp.async.cg.shared.global [%0], [%1], 16;" :: "r"(da), "l"(s) : "memory");
}
__device__ __forceinline__ void cpa16p(void* d, const void* s, bool pred) {
    uint32_t da = (uint32_t)__cvta_generic_to_shared(d);
    int sz = pred ? 16 : 0;
    asm volatile("cp.async.cg.shared.global [%0], [%1], 16, %2;" :: "r"(da), "l"(s), "r"(sz) : "memory");
}
#define CP_COMMIT() asm volatile("cp.async.commit_group;" ::: "memory")
#define CP_WAIT1()  asm volatile("cp.async.wait_group 1;" ::: "memory")
#define CP_WAIT0()  asm volatile("cp.async.wait_group 0;" ::: "memory")

// B stage: 128 N-rows x 64 K bf16 (hi+lo) for chunk kc
__device__ __forceinline__ void issue_B(char* smem, int wof, int K, int n0, int kc, int tid) {
    __nv_bfloat16* Bh = (__nv_bfloat16*)(smem + OFF_BH);
    __nv_bfloat16* Bl = (__nv_bfloat16*)(smem + OFF_BL);
    const __nv_bfloat16* sh = g_wb + wof + (size_t)n0 * K + kc;
    const __nv_bfloat16* sl = sh + WB_HALF;
    for (int i = tid; i < 1024; i += 128) {
        int n = i >> 3, kq = (i & 7) * 8;
        cpa16(Bh + n * LD + kq, sh + (size_t)n * K + kq);
        cpa16(Bl + n * LD + kq, sl + (size_t)n * K + kq);
    }
}

// convert fp32 staging -> hi/lo bf16 (thread reads only what it copied)
__device__ __forceinline__ void conv_A(char* smem, int tid, const float* rowscale) {
    const float* Af = (const float*)(smem + OFF_AF);
    __nv_bfloat16* Ah = (__nv_bfloat16*)smem;
    __nv_bfloat16* Al = (__nv_bfloat16*)(smem + OFF_AL);
    for (int i = tid; i < 2048; i += 128) {
        int r = i >> 4, q = (i & 15) * 4;
        float4 v = *(const float4*)(Af + r * LDF + q);
        if (rowscale) {
            float s = rowscale[r];
            v.x *= s; v.y *= s; v.z *= s; v.w *= s;
        }
        split4(v, Ah + r * LD + q, Al + r * LD + q);
    }
}

__device__ __forceinline__ void warp_gemm64(const char* smem, FragC acc[4][4], int wm, int wn) {
    const __nv_bfloat16* Ah = (const __nv_bfloat16*)smem;
    const __nv_bfloat16* Al = (const __nv_bfloat16*)(smem + OFF_AL);
    const __nv_bfloat16* Bh = (const __nv_bfloat16*)(smem + OFF_BH);
    const __nv_bfloat16* Bl = (const __nv_bfloat16*)(smem + OFF_BL);
#pragma unroll
    for (int kk = 0; kk < 64; kk += 16) {
        wmma::fragment<wmma::matrix_a, 16, 16, 16, __nv_bfloat16, wmma::row_major> ah[4], al[4];
#pragma unroll
        for (int mi = 0; mi < 4; mi++) {
            wmma::load_matrix_sync(ah[mi], Ah + (wm * 64 + mi * 16) * LD + kk, LD);
            wmma::load_matrix_sync(al[mi], Al + (wm * 64 + mi * 16) * LD + kk, LD);
        }
#pragma unroll
        for (int ni = 0; ni < 4; ni++) {
            wmma::fragment<wmma::matrix_b, 16, 16, 16, __nv_bfloat16, wmma::col_major> bh, bl;
            wmma::load_matrix_sync(bh, Bh + (wn * 64 + ni * 16) * LD + kk, LD);
            wmma::load_matrix_sync(bl, Bl + (wn * 64 + ni * 16) * LD + kk, LD);
#pragma unroll
            for (int mi = 0; mi < 4; mi++) {
                wmma::mma_sync(acc[mi][ni], ah[mi], bh, acc[mi][ni]);
                wmma::mma_sync(acc[mi][ni], al[mi], bh, acc[mi][ni]);
                wmma::mma_sync(acc[mi][ni], ah[mi], bl, acc[mi][ni]);
            }
        }
    }
}

// pipelined GEMM: A(c+1)/B(c) cp.async overlap MMA(c-1)/convert(c)
template<class FA>
__device__ __forceinline__ void run_gemm(int C, FA&& issueA, char* smem,
                                         int wof, int K, int n0,
                                         FragC acc[4][4], int wm, int wn, int tid,
                                         const float* rowscale) {
    issueA(0); CP_COMMIT();
    issue_B(smem, wof, K, n0, 0, tid); CP_COMMIT();
    CP_WAIT0(); __syncthreads();
    conv_A(smem, tid, rowscale);
    if (C > 1) { issueA(1); CP_COMMIT(); }
    __syncthreads();
    warp_gemm64(smem, acc, wm, wn);
    for (int c = 1; c < C; c++) {
        __syncthreads();                       // all done with B(c-1), Ah/Al
        issue_B(smem, wof, K, n0, c * 64, tid); CP_COMMIT();   // pending {A(c), B(c)}
        CP_WAIT1();                            // A(c) landed
        conv_A(smem, tid, rowscale);
        if (c + 1 < C) { issueA(c + 1); CP_COMMIT(); CP_WAIT1(); }  // retires B(c)
        else CP_WAIT0();
        __syncthreads();
        warp_gemm64(smem, acc, wm, wn);
    }
}

__device__ __forceinline__ void store_warpC(float* Cw, FragC acc[4][4]) {
#pragma unroll
    for (int mi = 0; mi < 4; mi++)
#pragma unroll
        for (int ni = 0; ni < 4; ni++)
            wmma::store_matrix_sync(Cw + (mi * 16) * 64 + ni * 16, acc[mi][ni], 64,
                                    wmma::mem_row_major);
}

#define GEMM_VARS() \
    extern __shared__ char smem[]; \
    float* Af = (float*)(smem + OFF_AF); \
    int tid = threadIdx.x, lane = tid & 31, w = tid >> 5, wm = w & 1, wn = w >> 1; \
    int ny = blockIdx.y; \
    FragC acc[4][4]; \
    _Pragma("unroll") for (int mi = 0; mi < 4; mi++) \
    _Pragma("unroll") for (int ni = 0; ni < 4; ni++) wmma::fill_fragment(acc[mi][ni], 0.f);

#define EPILOGUE_SETUP() \
    __syncthreads(); \
    float* Cw = (float*)smem + w * 4096; \
    store_warpC(Cw, acc); \
    __syncwarp();

// ------------------------- p: P = x @ W1a + b1 (K=128) ---------------------
__global__ __launch_bounds__(128, 2) void p_kernel(const float* __restrict__ x,
                                                   const float* __restrict__ b1) {
    GEMM_VARS();
    int m0 = blockIdx.x * 128;
    auto iA = [&](int c) {
        int kc = c * 64;
        for (int i = tid; i < 2048; i += 128) {
            int r = i >> 4, q = (i & 15) * 4;
            int n = m0 + r;
            cpa16p(Af + r * LDF + q, &x[(size_t)n * 128 + kc + q], n < NN);
        }
    };
    run_gemm(2, iA, smem, WOF_W1A, 128, ny * 128, acc, wm, wn, tid, nullptr);
    EPILOGUE_SETUP();
    for (int i2 = lane; i2 < 1024; i2 += 32) {
        int r = i2 >> 4, c = (i2 & 15) * 4;
        int n = m0 + wm * 64 + r;
        if (n < NN) {
            int col = ny * 128 + wn * 64 + c;
            float4 cv = *(float4*)(Cw + r * 64 + c);
            cv.x += __ldg(&b1[col]);     cv.y += __ldg(&b1[col + 1]);
            cv.z += __ldg(&b1[col + 2]); cv.w += __ldg(&b1[col + 3]);
            *(float4*)(g_P + (size_t)n * HID + col) = cv;
        }
    }
}

// ------------------------- edge: red-scatter relu(ea@W1b + P[row]) ---------
__global__ __launch_bounds__(128, 2) void edge_kernel(const float* __restrict__ ea,
                                                      const void* __restrict__ ei) {
    GEMM_VARS();
    __shared__ int rs[128], cs[128];
    int e0 = blockIdx.x * 128;
    rs[tid] = load_index(ei, e0 + tid);
    cs[tid] = load_index(ei, (long long)NE + e0 + tid);
    auto iA = [&](int c) {
        int kc = c * 64;
        for (int i = tid; i < 2048; i += 128) {
            int r = i >> 4, q = (i & 15) * 4;
            cpa16(Af + r * LDF + q, &ea[(size_t)(e0 + r) * 128 + kc + q]);
        }
    };
    run_gemm(2, iA, smem, WOF_W1B, 128, ny * 128, acc, wm, wn, tid, nullptr);
    EPILOGUE_SETUP();
    for (int i2 = lane; i2 < 1024; i2 += 32) {
        int r = i2 >> 4, c = (i2 & 15) * 4;
        int lr = wm * 64 + r;
        int col = ny * 128 + wn * 64 + c;
        float4 cv = *(float4*)(Cw + r * 64 + c);
        float4 pv = *(const float4*)(g_P + (size_t)rs[lr] * HID + col);
        float4 v;
        v.x = fmaxf(cv.x + pv.x, 0.f);
        v.y = fmaxf(cv.y + pv.y, 0.f);
        v.z = fmaxf(cv.z + pv.z, 0.f);
        v.w = fmaxf(cv.w + pv.w, 0.f);
        red_add4(g_agg + (size_t)cs[lr] * HID + col, v);
    }
    if (ny == 0) red_add1(&g_cnt[cs[tid]], 1.0f);
}

// ------------------------- agg2: (agg*rc) @ W2 + b2*ind (K=256) ------------
__global__ __launch_bounds__(128, 2) void agg2_kernel(const float* __restrict__ b2) {
    GEMM_VARS();
    __shared__ float rcs[128], inds[128];
    int m0 = blockIdx.x * 128;
    {
        int n = m0 + tid;
        float c = (n < NN) ? g_cnt[n] : 0.f;
        rcs[tid] = 1.0f / fmaxf(c, 1.0f);
        inds[tid] = (c > 0.f) ? 1.0f : 0.f;
    }
    auto iA = [&](int c) {
        int kc = c * 64;
        for (int i = tid; i < 2048; i += 128) {
            int r = i >> 4, q = (i & 15) * 4;
            int n = m0 + r;
            cpa16p(Af + r * LDF + q, &g_agg[(size_t)n * HID + kc + q], n < NN);
        }
    };
    run_gemm(4, iA, smem, WOF_W2, 256, ny * 128, acc, wm, wn, tid, rcs);
    EPILOGUE_SETUP();
    for (int i2 = lane; i2 < 1024; i2 += 32) {
        int r = i2 >> 4, c = (i2 & 15) * 4;
        int n = m0 + wm * 64 + r;
        if (n < NN) {
            int col = ny * 128 + wn * 64 + c;
            float ind = inds[wm * 64 + r];
            float4 cv = *(float4*)(Cw + r * 64 + c);
            cv.x += __ldg(&b2[col]) * ind;     cv.y += __ldg(&b2[col + 1]) * ind;
            cv.z += __ldg(&b2[col + 2]) * ind; cv.w += __ldg(&b2[col + 3]) * ind;
            *(float4*)(g_hagg + (size_t)n * HID + col) = cv;
        }
    }
}

// ------------------------- node1: t = relu([x||hagg||u]@W3+b3) -> g_P ------
__global__ __launch_bounds__(128, 2) void node1_kernel(const float* __restrict__ x,
                                                       const float* __restrict__ u,
                                                       const void* __restrict__ batch,
                                                       const float* __restrict__ b3) {
    GEMM_VARS();
    __shared__ int bts[128];
    int m0 = blockIdx.x * 128;
    {
        int n = m0 + tid;
        int b = (n < NN) ? load_index(batch, n) : 0;
        bts[tid] = (b < 64) ? b : 0;
    }
    __syncthreads();   // bts visible to all before issueA(0)
    auto iA = [&](int c) {
        int kc = c * 64;
        for (int i = tid; i < 2048; i += 128) {
            int r = i >> 4, q = (i & 15) * 4;
            int n = m0 + r;
            int k = kc + q;
            const float* src;
            if (k < 128)      src = &x[(size_t)n * 128 + k];
            else if (k < 384) src = &g_hagg[(size_t)n * HID + (k - 128)];
            else              src = &u[bts[r] * 64 + (k - 384)];
            cpa16p(Af + r * LDF + q, src, n < NN);
        }
    };
    run_gemm(7, iA, smem, WOF_W3, 448, ny * 128, acc, wm, wn, tid, nullptr);
    EPILOGUE_SETUP();
    for (int i2 = lane; i2 < 1024; i2 += 32) {
        int r = i2 >> 4, c = (i2 & 15) * 4;
        int n = m0 + wm * 64 + r;
        if (n < NN) {
            int col = ny * 128 + wn * 64 + c;
            float4 cv = *(float4*)(Cw + r * 64 + c);
            cv.x = fmaxf(cv.x + __ldg(&b3[col]), 0.f);
            cv.y = fmaxf(cv.y + __ldg(&b3[col + 1]), 0.f);
            cv.z = fmaxf(cv.z + __ldg(&b3[col + 2]), 0.f);
            cv.w = fmaxf(cv.w + __ldg(&b3[col + 3]), 0.f);
            *(float4*)(g_P + (size_t)n * HID + col) = cv;
        }
    }
}

// ------------------------- node2: out = t @ W4 + b4 (K=256, N=128) ---------
__global__ __launch_bounds__(128, 2) void node2_kernel(const float* __restrict__ b4,
                                                       float* __restrict__ out) {
    GEMM_VARS();
    (void)ny;
    int m0 = blockIdx.x * 128;
    auto iA = [&](int c) {
        int kc = c * 64;
        for (int i = tid; i < 2048; i += 128) {
            int r = i >> 4, q = (i & 15) * 4;
            int n = m0 + r;
            cpa16p(Af + r * LDF + q, &g_P[(size_t)n * HID + kc + q], n < NN);
        }
    };
    run_gemm(4, iA, smem, WOF_W4, 256, 0, acc, wm, wn, tid, nullptr);
    EPILOGUE_SETUP();
    for (int i2 = lane; i2 < 1024; i2 += 32) {
        int r = i2 >> 4, c = (i2 & 15) * 4;
        int n = m0 + wm * 64 + r;
        if (n < NN) {
            int col = wn * 64 + c;
            float4 cv = *(float4*)(Cw + r * 64 + c);
            cv.x += __ldg(&b4[col]);     cv.y += __ldg(&b4[col + 1]);
            cv.z += __ldg(&b4[col + 2]); cv.w += __ldg(&b4[col + 3]);
            *(float4*)(out + (size_t)n * 128 + col) = cv;
        }
    }
}

// ---------------------------------------------------------------------------
extern "C" void kernel_launch(void* const* d_in, const int* in_sizes, int n_in,
                              void* d_out, int out_size) {
    const float* x     = (const float*)d_in[0];
    const void*  ei    = d_in[1];
    const float* ea    = (const float*)d_in[2];
    const float* u     = (const float*)d_in[3];
    const void*  batch = d_in[4];
    const float* W1    = (const float*)d_in[5];
    const float* b1    = (const float*)d_in[6];
    const float* W2    = (const float*)d_in[7];
    const float* b2    = (const float*)d_in[8];
    const float* W3    = (const float*)d_in[9];
    const float* b3    = (const float*)d_in[10];
    const float* W4    = (const float*)d_in[11];
    const float* b4    = (const float*)d_in[12];
    float* out = (float*)d_out;

    static int attr_done = 0;
    if (!attr_done) {
        cudaFuncSetAttribute(p_kernel,     cudaFuncAttributeMaxDynamicSharedMemorySize, SMEM_TOTAL);
        cudaFuncSetAttribute(edge_kernel,  cudaFuncAttributeMaxDynamicSharedMemorySize, SMEM_TOTAL);
        cudaFuncSetAttribute(agg2_kernel,  cudaFuncAttributeMaxDynamicSharedMemorySize, SMEM_TOTAL);
        cudaFuncSetAttribute(node1_kernel, cudaFuncAttributeMaxDynamicSharedMemorySize, SMEM_TOTAL);
        cudaFuncSetAttribute(node2_kernel, cudaFuncAttributeMaxDynamicSharedMemorySize, SMEM_TOTAL);
        attr_done = 1;
    }

    int nblk = (NN + 127) / 128;
    dim3 g2(nblk, 2), ge(NE / 128, 2), g1(nblk, 1);
    zero_kernel<<<2048, 256>>>(ei);
    prep_kernel<<<512, 256>>>(W1, W2, W3, W4);
    p_kernel<<<g2, 128, SMEM_TOTAL>>>(x, b1);
    edge_kernel<<<ge, 128, SMEM_TOTAL>>>(ea, ei);
    agg2_kernel<<<g2, 128, SMEM_TOTAL>>>(b2);
    node1_kernel<<<g2, 128, SMEM_TOTAL>>>(x, u, batch, b3);
    node2_kernel<<<g1, 128, SMEM_TOTAL>>>(b4, out);
}